// round 2
// baseline (speedup 1.0000x reference)
#include <cuda_runtime.h>
#include <cuda_bf16.h>
#include <math.h>

// ---------------------------------------------------------------------------
// Sea_Attention fused implementation (fp32, round 1: fix pos-interp coord)
//
// Key simplification: _cbn is linear per-channel, so spatial means commute
// with it. We only ever compute x.mean over W / over H (tiny tensors) for the
// axial attention branches; the full q/k maps are never materialized.
//
// Pipeline:
//   prep      : fold scale into weights, build pos-interp tables
//   reduce    : xrow = x.mean(-1), xcol = x.mean(-2)      (layout [c][b*64+n])
//   gemm<0>   : axial q,k,v for both branches (+pos add)  (768x256 GEMM, P=1024)
//   attn      : 16-dim axial attention per (branch,b,head)
//   gemm<2>   : w_row/w_col cbn on relu(attn out)         (512x512 GEMM, P=1024)
//   gemm<1>   : v = cbn(wv,x), g1 = cbn(w_sc,x) fused     (768x256 GEMM, P=65536)
//   dw        : depthwise 3x3 + affine + relu -> g2
//   gemm<3>   : out = hsig(pw(g2)) * proj(relu(v+xxr+xxc)) (256x768 dual-acc GEMM)
// ---------------------------------------------------------------------------

#define DIMC   256
#define NHKD   128
#define DH     512
#define NH     8
#define KD     16
#define DD     64
#define BB     16
#define HH     64
#define WW     64
#define HWSZ   4096
#define NPIX   (BB*HWSZ)          // 65536
#define PAX    (BB*64)            // 1024 axial "pixels" per branch

// ---------------- scratch (device globals; no allocation allowed) ----------
__device__ float g_Wqkv[768*256];       // rows 0-127 q, 128-255 k, 256-767 v (scale folded)
__device__ float g_Wvg1[768*256];       // rows 0-511 v, 512-767 sc
__device__ float g_Wxx[2][512*512];     // w_row / w_col (scale folded)
__device__ float g_Wfin[256*768];       // [m][0:512]=proj, [512:768]=pw
__device__ float g_wdw[256*9];          // depthwise weights (scale folded)
__device__ float g_pos[4][128*64];      // 0 rowq, 1 rowk, 2 colq, 3 colk (interpolated)
__device__ float g_xm[2][256*1024];     // row/col means, [c][b*64+n]
__device__ float g_q[2][128*1024];      // axial q (+pos), [c][b*64+n]
__device__ float g_k[2][128*1024];
__device__ float g_vax[2][512*1024];    // axial v
__device__ float g_ax[2][512*1024];     // attention output (pre-relu), [c][b*64+n]
__device__ float g_xx[2][BB*512*64];    // after w_row/w_col cbn, [b][c][n]
__device__ float g_v[BB*512*4096];      // full v map  [b][c][hw]
__device__ float g_g1[BB*256*4096];     // gate intermediate 1
__device__ float g_g2[BB*256*4096];     // gate intermediate 2 (post dw+relu)

struct P32 { const float* p[32]; };

// ---------------- prep: fold scales into weights, build pos tables ----------
__global__ void prep_kernel(P32 ps) {
    int i = blockIdx.x * 256 + threadIdx.x;
    // seg 0: Wqkv (768x256)
    if (i < 196608) {
        int r = i >> 8, k = i & 255;
        float v;
        if (r < 128)      v = ps.p[2][r]       * ps.p[1][r*256+k];
        else if (r < 256) v = ps.p[5][r-128]   * ps.p[4][(r-128)*256+k];
        else              v = ps.p[8][r-256]   * ps.p[7][(r-256)*256+k];
        g_Wqkv[i] = v; return;
    }
    i -= 196608;
    // seg 1: Wvg1 (768x256)
    if (i < 196608) {
        int r = i >> 8, k = i & 255;
        float v = (r < 512) ? ps.p[8][r] * ps.p[7][r*256+k]
                            : ps.p[24][r-512] * ps.p[23][(r-512)*256+k];
        g_Wvg1[i] = v; return;
    }
    i -= 196608;
    // seg 2/3: Wxx row / col (512x512 each)
    if (i < 262144) { int r = i >> 9; g_Wxx[0][i] = ps.p[15][r] * ps.p[14][i]; return; }
    i -= 262144;
    if (i < 262144) { int r = i >> 9; g_Wxx[1][i] = ps.p[18][r] * ps.p[17][i]; return; }
    i -= 262144;
    // seg 4: Wfin (256x768)
    if (i < 196608) {
        int r = i / 768, c = i % 768;
        float v = (c < 512) ? ps.p[21][r] * ps.p[20][r*512+c]
                            : ps.p[30][r] * ps.p[29][r*256+(c-512)];
        g_Wfin[i] = v; return;
    }
    i -= 196608;
    // seg 5: dw weights (256x9)
    if (i < 2304) { g_wdw[i] = ps.p[27][i/9] * ps.p[26][i]; return; }
    i -= 2304;
    // seg 6: pos interpolation tables (4 x 128 x 64)
    if (i < 32768) {
        int t = i >> 13, rest = i & 8191;
        int c = rest >> 6, n = rest & 63;
        // coords = (n + 0.5) * (16/64) - 0.5 = 0.25*n - 0.375   (was -0.25: BUG)
        float coord = 0.25f * (float)n - 0.375f;
        coord = fminf(fmaxf(coord, 0.0f), 15.0f);
        int lo = (int)floorf(coord);
        int hi = min(lo + 1, 15);
        float tf = coord - (float)lo;
        const float* src = ps.p[10 + t];
        g_pos[t][c*64 + n] = src[c*16+lo] * (1.0f - tf) + src[c*16+hi] * tf;
    }
}

// ---------------- reduce: row & col means of x --------------------------
__global__ void reduce_kernel(const float* __restrict__ x) {
    int bc = blockIdx.x;                  // b*256 + c
    int b = bc >> 8, c = bc & 255;
    __shared__ float sm[64 * 65];
    int t = threadIdx.x;                  // 256 threads
    const float* xp = x + (size_t)bc * 4096;
    for (int i = t; i < 4096; i += 256)
        sm[(i >> 6) * 65 + (i & 63)] = xp[i];
    __syncthreads();
    if (t < 64) {                         // row branch value at h=t: mean over w
        float s = 0.f;
        #pragma unroll
        for (int w = 0; w < 64; w++) s += sm[t*65 + w];
        g_xm[0][c*1024 + b*64 + t] = s * (1.0f/64.0f);
    } else if (t < 128) {                 // col branch value at w: mean over h
        int w = t - 64;
        float s = 0.f;
        #pragma unroll
        for (int h = 0; h < 64; h++) s += sm[h*65 + w];
        g_xm[1][c*1024 + b*64 + w] = s * (1.0f/64.0f);
    }
}

// ---------------- axial attention -------------------------------------
__global__ void attn_kernel() {
    int bid = blockIdx.x;                 // br*128 + b*8 + h
    int br = bid >> 7, b = (bid >> 3) & 15, h = bid & 7;
    __shared__ float qs[16][64], ks[16][64], vs[64][64], ps[64][65];
    int t = threadIdx.x;                  // 64 threads, thread = n
    #pragma unroll
    for (int kd = 0; kd < 16; kd++) {
        qs[kd][t] = g_q[br][(h*16+kd)*1024 + b*64 + t];
        ks[kd][t] = g_k[br][(h*16+kd)*1024 + b*64 + t];
    }
    for (int d = 0; d < 64; d++)
        vs[d][t] = g_vax[br][(h*64+d)*1024 + b*64 + t];
    __syncthreads();
    float qreg[16];
    #pragma unroll
    for (int kd = 0; kd < 16; kd++) qreg[kd] = qs[kd][t];
    float mx = -1e30f;
    for (int m = 0; m < 64; m++) {
        float s = 0.f;
        #pragma unroll
        for (int kd = 0; kd < 16; kd++) s = fmaf(qreg[kd], ks[kd][m], s);
        s *= 0.25f;                       // KEY_DIM^-0.5
        ps[t][m] = s;
        mx = fmaxf(mx, s);
    }
    float sum = 0.f;
    for (int m = 0; m < 64; m++) {
        float e = __expf(ps[t][m] - mx);
        ps[t][m] = e;
        sum += e;
    }
    float inv = 1.0f / sum;
    for (int d = 0; d < 64; d++) {
        float o = 0.f;
        for (int m = 0; m < 64; m++) o = fmaf(ps[t][m], vs[d][m], o);
        g_ax[br][(h*64+d)*1024 + b*64 + t] = o * inv;
    }
}

// ---------------- depthwise 3x3 + affine + relu -------------------------
__global__ void dw_kernel(const float* __restrict__ b_dw) {
    int bc = blockIdx.x;                  // b*256 + c
    int c = bc & 255;
    __shared__ float sm[64][65];
    const float* gp = &g_g1[(size_t)bc * 4096];
    int t = threadIdx.x;
    for (int i = t; i < 4096; i += 256) sm[i >> 6][i & 63] = gp[i];
    __syncthreads();
    float w9[9];
    #pragma unroll
    for (int j = 0; j < 9; j++) w9[j] = g_wdw[c*9 + j];
    float bias = b_dw[c];
    for (int i = t; i < 4096; i += 256) {
        int h = i >> 6, w = i & 63;
        float s = 0.f;
        #pragma unroll
        for (int di = 0; di < 3; di++) {
            int hh = h + di - 1;
            if ((unsigned)hh >= 64u) continue;
            #pragma unroll
            for (int dj = 0; dj < 3; dj++) {
                int ww = w + dj - 1;
                if ((unsigned)ww >= 64u) continue;
                s = fmaf(sm[hh][ww], w9[di*3 + dj], s);
            }
        }
        g_g2[(size_t)bc * 4096 + i] = fmaxf(s + bias, 0.0f);
    }
}

// ---------------- tiled GEMM (BM=128, BN=64, BK=16, 256 threads) --------
// MODE 0: axial qkv   (K=256, P=1024, z=branch)
// MODE 1: v + g1      (K=256, P=65536)
// MODE 2: w_row/w_col (K=512, P=1024, z=branch, relu on input)
// MODE 3: final fused (K=768 dual-acc, P=65536, writes d_out)
#define BM 128
#define BN 64
#define BK 16

__device__ __forceinline__ float hsig(float x) {
    return fminf(fmaxf(x + 3.0f, 0.0f), 6.0f) * (1.0f/6.0f);
}

__device__ __forceinline__ void rank1(float (&A)[8][4], float4 a0, float4 a1, float4 b) {
    float ar[8] = {a0.x, a0.y, a0.z, a0.w, a1.x, a1.y, a1.z, a1.w};
    #pragma unroll
    for (int r = 0; r < 8; r++) {
        A[r][0] = fmaf(ar[r], b.x, A[r][0]);
        A[r][1] = fmaf(ar[r], b.y, A[r][1]);
        A[r][2] = fmaf(ar[r], b.z, A[r][2]);
        A[r][3] = fmaf(ar[r], b.w, A[r][3]);
    }
}

template <int MODE>
__global__ void __launch_bounds__(256, 2) gemm_k(
        const float* __restrict__ b0, const float* __restrict__ b1,
        const float* __restrict__ b2, const float* __restrict__ xin,
        float* __restrict__ outp) {
    constexpr int K = (MODE <= 1) ? 256 : (MODE == 2 ? 512 : 768);
    __shared__ float As[BK][BM + 4];
    __shared__ float Bs[BK][BN + 4];
    const int tid = threadIdx.x;
    const int bx = blockIdx.x, by = blockIdx.y, bz = blockIdx.z;
    const int ty8 = (tid >> 4) << 3;
    const int tx4 = (tid & 15) << 2;
    const int m0 = by * BM;
    const int pt = bx * BN;
    const float* Wm = (MODE == 0) ? g_Wqkv
                    : (MODE == 1) ? g_Wvg1
                    : (MODE == 2) ? g_Wxx[bz] : g_Wfin;
    const int wml = tid >> 1;             // 0..127
    const int wkg = (tid & 1) * 8;        // 0 or 8
    const int xkk = tid >> 4;             // 0..15
    const int xpl = (tid & 15) << 2;      // 0..60

    float acc[8][4];
    float accB[8][4];
    #pragma unroll
    for (int r = 0; r < 8; r++)
        #pragma unroll
        for (int j = 0; j < 4; j++) { acc[r][j] = 0.f; accB[r][j] = 0.f; }

    int b_ = 0, hw0 = 0, h_ = 0;
    if (MODE == 1 || MODE == 3) { b_ = pt >> 12; hw0 = pt & 4095; h_ = hw0 >> 6; }

    for (int kt = 0; kt < K; kt += BK) {
        // global -> regs
        const float* wp = &Wm[(m0 + wml) * K + kt + wkg];
        float4 w0 = *(const float4*)wp;
        float4 w1 = *(const float4*)(wp + 4);
        int k = kt + xkk;
        float4 xv;
        if (MODE == 0) {
            xv = *(const float4*)&g_xm[bz][k*1024 + pt + xpl];
        } else if (MODE == 1) {
            xv = *(const float4*)&xin[(size_t)((b_ << 8) + k) * 4096 + hw0 + xpl];
        } else if (MODE == 2) {
            float4 t4 = *(const float4*)&g_ax[bz][k*1024 + pt + xpl];
            xv.x = fmaxf(t4.x, 0.f); xv.y = fmaxf(t4.y, 0.f);
            xv.z = fmaxf(t4.z, 0.f); xv.w = fmaxf(t4.w, 0.f);
        } else {
            if (k < 512) {
                float4 v4 = *(const float4*)&g_v[((size_t)(b_*512 + k) << 12) + hw0 + xpl];
                float4 c4 = *(const float4*)&g_xx[1][(b_*512 + k)*64 + xpl];
                float  xr = g_xx[0][(b_*512 + k)*64 + h_];
                xv.x = fmaxf(v4.x + c4.x + xr, 0.f);
                xv.y = fmaxf(v4.y + c4.y + xr, 0.f);
                xv.z = fmaxf(v4.z + c4.z + xr, 0.f);
                xv.w = fmaxf(v4.w + c4.w + xr, 0.f);
            } else {
                xv = *(const float4*)&g_g2[((size_t)(b_*256 + (k - 512)) << 12) + hw0 + xpl];
            }
        }
        __syncthreads();
        // regs -> smem (W transposed)
        As[wkg+0][wml] = w0.x; As[wkg+1][wml] = w0.y;
        As[wkg+2][wml] = w0.z; As[wkg+3][wml] = w0.w;
        As[wkg+4][wml] = w1.x; As[wkg+5][wml] = w1.y;
        As[wkg+6][wml] = w1.z; As[wkg+7][wml] = w1.w;
        *(float4*)&Bs[xkk][xpl] = xv;
        __syncthreads();
        // compute
        if (MODE == 3 && kt >= 512) {
            #pragma unroll
            for (int u = 0; u < BK; u++) {
                float4 a0 = *(const float4*)&As[u][ty8];
                float4 a1 = *(const float4*)&As[u][ty8 + 4];
                float4 bv = *(const float4*)&Bs[u][tx4];
                rank1(accB, a0, a1, bv);
            }
        } else {
            #pragma unroll
            for (int u = 0; u < BK; u++) {
                float4 a0 = *(const float4*)&As[u][ty8];
                float4 a1 = *(const float4*)&As[u][ty8 + 4];
                float4 bv = *(const float4*)&Bs[u][tx4];
                rank1(acc, a0, a1, bv);
            }
        }
    }

    // epilogue
    #pragma unroll
    for (int r = 0; r < 8; r++) {
        int m = m0 + ty8 + r;
        if (MODE == 0) {
            float4 o;
            if (m < 128) {
                float4 pv = *(const float4*)&g_pos[bz ? 2 : 0][m*64 + tx4];
                float bb = b0[m];
                o.x = acc[r][0] + bb + pv.x; o.y = acc[r][1] + bb + pv.y;
                o.z = acc[r][2] + bb + pv.z; o.w = acc[r][3] + bb + pv.w;
                *(float4*)&g_q[bz][m*1024 + pt + tx4] = o;
            } else if (m < 256) {
                int mm = m - 128;
                float4 pv = *(const float4*)&g_pos[bz ? 3 : 1][mm*64 + tx4];
                float bb = b1[mm];
                o.x = acc[r][0] + bb + pv.x; o.y = acc[r][1] + bb + pv.y;
                o.z = acc[r][2] + bb + pv.z; o.w = acc[r][3] + bb + pv.w;
                *(float4*)&g_k[bz][mm*1024 + pt + tx4] = o;
            } else {
                int mm = m - 256;
                float bb = b2[mm];
                o.x = acc[r][0] + bb; o.y = acc[r][1] + bb;
                o.z = acc[r][2] + bb; o.w = acc[r][3] + bb;
                *(float4*)&g_vax[bz][mm*1024 + pt + tx4] = o;
            }
        } else if (MODE == 1) {
            float4 o;
            if (m < 512) {
                float bb = b1[m];
                o.x = acc[r][0] + bb; o.y = acc[r][1] + bb;
                o.z = acc[r][2] + bb; o.w = acc[r][3] + bb;
                *(float4*)&g_v[((size_t)(b_*512 + m) << 12) + hw0 + tx4] = o;
            } else {
                int mm = m - 512;
                float bb = b2[mm];
                o.x = acc[r][0] + bb; o.y = acc[r][1] + bb;
                o.z = acc[r][2] + bb; o.w = acc[r][3] + bb;
                *(float4*)&g_g1[((size_t)(b_*256 + mm) << 12) + hw0 + tx4] = o;
            }
        } else if (MODE == 2) {
            float bb = (bz ? b2 : b1)[m];
            float4 o;
            o.x = acc[r][0] + bb; o.y = acc[r][1] + bb;
            o.z = acc[r][2] + bb; o.w = acc[r][3] + bb;
            int bidx = pt >> 6;          // batch (P=1024, tile inside one b)
            *(float4*)&g_xx[bz][(bidx*512 + m)*64 + tx4] = o;
        } else {
            float bp = b1[m], bw = b2[m];
            float4 o;
            o.x = (acc[r][0] + bp) * hsig(accB[r][0] + bw);
            o.y = (acc[r][1] + bp) * hsig(accB[r][1] + bw);
            o.z = (acc[r][2] + bp) * hsig(accB[r][2] + bw);
            o.w = (acc[r][3] + bp) * hsig(accB[r][3] + bw);
            *(float4*)&outp[((size_t)(b_*256 + m) << 12) + hw0 + tx4] = o;
        }
    }
}

// ---------------------------------------------------------------------------
extern "C" void kernel_launch(void* const* d_in, const int* in_sizes, int n_in,
                              void* d_out, int out_size) {
    (void)in_sizes; (void)n_in; (void)out_size;
    P32 ps;
    for (int i = 0; i < 32; i++) ps.p[i] = (const float*)d_in[i];
    const float* x      = ps.p[0];
    const float* bq     = ps.p[3];
    const float* bk     = ps.p[6];
    const float* bv     = ps.p[9];
    const float* b_row  = ps.p[16];
    const float* b_col  = ps.p[19];
    const float* b_proj = ps.p[22];
    const float* b_sc   = ps.p[25];
    const float* b_dw   = ps.p[28];
    const float* b_pw   = ps.p[31];
    float* out = (float*)d_out;

    prep_kernel<<<4489, 256>>>(ps);
    reduce_kernel<<<4096, 256>>>(x);
    gemm_k<0><<<dim3(16, 6, 2), 256>>>(bq, bk, bv, nullptr, nullptr);
    attn_kernel<<<256, 64>>>();
    gemm_k<2><<<dim3(16, 4, 2), 256>>>(nullptr, b_row, b_col, nullptr, nullptr);
    gemm_k<1><<<dim3(1024, 6, 1), 256>>>(nullptr, bv, b_sc, x, nullptr);
    dw_kernel<<<4096, 256>>>(b_dw);
    gemm_k<3><<<dim3(1024, 2, 1), 256>>>(nullptr, b_proj, b_pw, nullptr, out);
}

// round 5
// speedup vs baseline: 1.6802x; 1.6802x over previous
#include <cuda_runtime.h>
#include <cuda_bf16.h>
#include <math.h>
#include <stdint.h>

// ---------------------------------------------------------------------------
// Sea_Attention fused, round 4: heavy GEMMs via mma.sync bf16 (3-term split).
// (tcgen05 unavailable: harness PTX target is compute_103 without 'a' features)
//
//   prep      : fold scales; pos tables; bf16 hi/lo split of Wvg1 / Wfin
//   reduce    : row/col means of x
//   gemm_k<0> : axial qkv (fp32 SIMT, tiny)
//   attn      : axial attention
//   gemm_k<2> : w_row/w_col cbn (fp32 SIMT, tiny)
//   mm<1>     : v = cbn(wv,x), g1 = cbn(w_sc,x)            [HMMA]
//   dw        : depthwise 3x3 + affine + relu (g1 -> g2)
//   mm<3>     : proj(relu(v+xx)) + b_proj -> g1 (reused)   [HMMA]
//   mm<4>     : out = g1 * hsig(pw(g2) + b_pw)             [HMMA]
// ---------------------------------------------------------------------------

#define BB 16

// ---------------- device scratch ----------------
__device__ float g_Wqkv[768*256];
__device__ float g_Wxx[2][512*512];
__device__ __nv_bfloat16 g_Wvg1_h[768*256];
__device__ __nv_bfloat16 g_Wvg1_l[768*256];
__device__ __nv_bfloat16 g_Wfin_h[256*768];
__device__ __nv_bfloat16 g_Wfin_l[256*768];
__device__ float g_wdw[256*9];
__device__ float g_pos[4][128*64];
__device__ float g_xm[2][256*1024];
__device__ float g_q[2][128*1024];
__device__ float g_k[2][128*1024];
__device__ float g_vax[2][512*1024];
__device__ float g_ax[2][512*1024];
__device__ float g_xx[2][BB*512*64];
__device__ float g_v[(size_t)BB*512*4096];
__device__ float g_g1[(size_t)BB*256*4096];   // gate int.1, then proj results
__device__ float g_g2[(size_t)BB*256*4096];

struct P32 { const float* p[32]; };

__device__ __forceinline__ float hsig(float x) {
    return fminf(fmaxf(x + 3.0f, 0.0f), 6.0f) * (1.0f / 6.0f);
}

__device__ __forceinline__ void mma16816(float (&d)[4], const uint32_t (&a)[4],
                                         uint32_t b0, uint32_t b1) {
    asm volatile(
        "mma.sync.aligned.m16n8k16.row.col.f32.bf16.bf16.f32 "
        "{%0,%1,%2,%3}, {%4,%5,%6,%7}, {%8,%9}, {%0,%1,%2,%3};"
        : "+f"(d[0]), "+f"(d[1]), "+f"(d[2]), "+f"(d[3])
        : "r"(a[0]), "r"(a[1]), "r"(a[2]), "r"(a[3]), "r"(b0), "r"(b1));
}

// ---------------- prep ----------------
__global__ void prep_kernel(P32 ps) {
    int i = blockIdx.x * 256 + threadIdx.x;
    if (i < 196608) {                       // Wqkv fp32
        int r = i >> 8, k = i & 255;
        float v;
        if (r < 128)      v = ps.p[2][r]     * ps.p[1][r*256+k];
        else if (r < 256) v = ps.p[5][r-128] * ps.p[4][(r-128)*256+k];
        else              v = ps.p[8][r-256] * ps.p[7][(r-256)*256+k];
        g_Wqkv[i] = v; return;
    }
    i -= 196608;
    if (i < 196608) {                       // Wvg1 bf16 hi/lo
        int r = i >> 8, k = i & 255;
        float v = (r < 512) ? ps.p[8][r] * ps.p[7][r*256+k]
                            : ps.p[24][r-512] * ps.p[23][(r-512)*256+k];
        __nv_bfloat16 h = __float2bfloat16_rn(v);
        g_Wvg1_h[i] = h;
        g_Wvg1_l[i] = __float2bfloat16_rn(v - __bfloat162float(h));
        return;
    }
    i -= 196608;
    if (i < 262144) { int r = i >> 9; g_Wxx[0][i] = ps.p[15][r] * ps.p[14][i]; return; }
    i -= 262144;
    if (i < 262144) { int r = i >> 9; g_Wxx[1][i] = ps.p[18][r] * ps.p[17][i]; return; }
    i -= 262144;
    if (i < 196608) {                       // Wfin bf16 hi/lo
        int r = i / 768, c = i % 768;
        float v = (c < 512) ? ps.p[21][r] * ps.p[20][r*512+c]
                            : ps.p[30][r] * ps.p[29][r*256+(c-512)];
        __nv_bfloat16 h = __float2bfloat16_rn(v);
        g_Wfin_h[i] = h;
        g_Wfin_l[i] = __float2bfloat16_rn(v - __bfloat162float(h));
        return;
    }
    i -= 196608;
    if (i < 2304) { g_wdw[i] = ps.p[27][i/9] * ps.p[26][i]; return; }
    i -= 2304;
    if (i < 32768) {
        int t = i >> 13, rest = i & 8191;
        int c = rest >> 6, n = rest & 63;
        float coord = 0.25f * (float)n - 0.375f;
        coord = fminf(fmaxf(coord, 0.0f), 15.0f);
        int lo = (int)floorf(coord);
        int hi = min(lo + 1, 15);
        float tf = coord - (float)lo;
        const float* src = ps.p[10 + t];
        g_pos[t][c*64 + n] = src[c*16+lo] * (1.0f - tf) + src[c*16+hi] * tf;
    }
}

// ---------------- reduce ----------------
__global__ void reduce_kernel(const float* __restrict__ x) {
    int bc = blockIdx.x;
    int b = bc >> 8, c = bc & 255;
    __shared__ float sm[64 * 65];
    int t = threadIdx.x;
    const float* xp = x + (size_t)bc * 4096;
    for (int i = t; i < 4096; i += 256)
        sm[(i >> 6) * 65 + (i & 63)] = xp[i];
    __syncthreads();
    if (t < 64) {
        float s = 0.f;
        #pragma unroll
        for (int w = 0; w < 64; w++) s += sm[t*65 + w];
        g_xm[0][c*1024 + b*64 + t] = s * (1.0f/64.0f);
    } else if (t < 128) {
        int w = t - 64;
        float s = 0.f;
        #pragma unroll
        for (int h = 0; h < 64; h++) s += sm[h*65 + w];
        g_xm[1][c*1024 + b*64 + w] = s * (1.0f/64.0f);
    }
}

// ---------------- axial attention ----------------
__global__ void attn_kernel() {
    int bid = blockIdx.x;
    int br = bid >> 7, b = (bid >> 3) & 15, h = bid & 7;
    __shared__ float qs[16][64], ks[16][64], vs[64][64], ps[64][65];
    int t = threadIdx.x;
    #pragma unroll
    for (int kd = 0; kd < 16; kd++) {
        qs[kd][t] = g_q[br][(h*16+kd)*1024 + b*64 + t];
        ks[kd][t] = g_k[br][(h*16+kd)*1024 + b*64 + t];
    }
    for (int d = 0; d < 64; d++)
        vs[d][t] = g_vax[br][(h*64+d)*1024 + b*64 + t];
    __syncthreads();
    float qreg[16];
    #pragma unroll
    for (int kd = 0; kd < 16; kd++) qreg[kd] = qs[kd][t];
    float mx = -1e30f;
    for (int m = 0; m < 64; m++) {
        float s = 0.f;
        #pragma unroll
        for (int kd = 0; kd < 16; kd++) s = fmaf(qreg[kd], ks[kd][m], s);
        s *= 0.25f;
        ps[t][m] = s;
        mx = fmaxf(mx, s);
    }
    float sum = 0.f;
    for (int m = 0; m < 64; m++) {
        float e = __expf(ps[t][m] - mx);
        ps[t][m] = e;
        sum += e;
    }
    float inv = 1.0f / sum;
    for (int d = 0; d < 64; d++) {
        float o = 0.f;
        for (int m = 0; m < 64; m++) o = fmaf(ps[t][m], vs[d][m], o);
        g_ax[br][(h*64+d)*1024 + b*64 + t] = o * inv;
    }
}

// ---------------- depthwise ----------------
__global__ void dw_kernel(const float* __restrict__ b_dw) {
    int bc = blockIdx.x;
    int c = bc & 255;
    __shared__ float sm[64][65];
    const float* gp = &g_g1[(size_t)bc * 4096];
    int t = threadIdx.x;
    for (int i = t; i < 4096; i += 256) sm[i >> 6][i & 63] = gp[i];
    __syncthreads();
    float w9[9];
    #pragma unroll
    for (int j = 0; j < 9; j++) w9[j] = g_wdw[c*9 + j];
    float bias = b_dw[c];
    for (int i = t; i < 4096; i += 256) {
        int h = i >> 6, w = i & 63;
        float s = 0.f;
        #pragma unroll
        for (int di = 0; di < 3; di++) {
            int hh = h + di - 1;
            if ((unsigned)hh >= 64u) continue;
            #pragma unroll
            for (int dj = 0; dj < 3; dj++) {
                int ww = w + dj - 1;
                if ((unsigned)ww >= 64u) continue;
                s = fmaf(sm[hh][ww], w9[di*3 + dj], s);
            }
        }
        g_g2[(size_t)bc * 4096 + i] = fmaxf(s + bias, 0.0f);
    }
}

// ---------------- small SIMT GEMM (modes 0 & 2) ----------------
#define BM 128
#define BN 64
#define BK 16

__device__ __forceinline__ void rank1(float (&A)[8][4], float4 a0, float4 a1, float4 b) {
    float ar[8] = {a0.x, a0.y, a0.z, a0.w, a1.x, a1.y, a1.z, a1.w};
    #pragma unroll
    for (int r = 0; r < 8; r++) {
        A[r][0] = fmaf(ar[r], b.x, A[r][0]);
        A[r][1] = fmaf(ar[r], b.y, A[r][1]);
        A[r][2] = fmaf(ar[r], b.z, A[r][2]);
        A[r][3] = fmaf(ar[r], b.w, A[r][3]);
    }
}

template <int MODE>
__global__ void __launch_bounds__(256, 2) gemm_k(
        const float* __restrict__ b0, const float* __restrict__ b1,
        const float* __restrict__ b2) {
    constexpr int K = (MODE == 0) ? 256 : 512;
    __shared__ float As[BK][BM + 4];
    __shared__ float Bs[BK][BN + 4];
    const int tid = threadIdx.x;
    const int bx = blockIdx.x, by = blockIdx.y, bz = blockIdx.z;
    const int ty8 = (tid >> 4) << 3;
    const int tx4 = (tid & 15) << 2;
    const int m0 = by * BM;
    const int pt = bx * BN;
    const float* Wm = (MODE == 0) ? g_Wqkv : g_Wxx[bz];
    const int wml = tid >> 1;
    const int wkg = (tid & 1) * 8;
    const int xkk = tid >> 4;
    const int xpl = (tid & 15) << 2;

    float acc[8][4];
    #pragma unroll
    for (int r = 0; r < 8; r++)
        #pragma unroll
        for (int j = 0; j < 4; j++) acc[r][j] = 0.f;

    for (int kt = 0; kt < K; kt += BK) {
        const float* wp = &Wm[(m0 + wml) * K + kt + wkg];
        float4 w0 = *(const float4*)wp;
        float4 w1 = *(const float4*)(wp + 4);
        int k = kt + xkk;
        float4 xv;
        if (MODE == 0) {
            xv = *(const float4*)&g_xm[bz][k*1024 + pt + xpl];
        } else {
            float4 t4 = *(const float4*)&g_ax[bz][k*1024 + pt + xpl];
            xv.x = fmaxf(t4.x, 0.f); xv.y = fmaxf(t4.y, 0.f);
            xv.z = fmaxf(t4.z, 0.f); xv.w = fmaxf(t4.w, 0.f);
        }
        __syncthreads();
        As[wkg+0][wml] = w0.x; As[wkg+1][wml] = w0.y;
        As[wkg+2][wml] = w0.z; As[wkg+3][wml] = w0.w;
        As[wkg+4][wml] = w1.x; As[wkg+5][wml] = w1.y;
        As[wkg+6][wml] = w1.z; As[wkg+7][wml] = w1.w;
        *(float4*)&Bs[xkk][xpl] = xv;
        __syncthreads();
        #pragma unroll
        for (int u = 0; u < BK; u++) {
            float4 a0 = *(const float4*)&As[u][ty8];
            float4 a1 = *(const float4*)&As[u][ty8 + 4];
            float4 bv = *(const float4*)&Bs[u][tx4];
            rank1(acc, a0, a1, bv);
        }
    }

    #pragma unroll
    for (int r = 0; r < 8; r++) {
        int m = m0 + ty8 + r;
        if (MODE == 0) {
            float4 o;
            if (m < 128) {
                float4 pv = *(const float4*)&g_pos[bz ? 2 : 0][m*64 + tx4];
                float bb = b0[m];
                o.x = acc[r][0] + bb + pv.x; o.y = acc[r][1] + bb + pv.y;
                o.z = acc[r][2] + bb + pv.z; o.w = acc[r][3] + bb + pv.w;
                *(float4*)&g_q[bz][m*1024 + pt + tx4] = o;
            } else if (m < 256) {
                int mm = m - 128;
                float4 pv = *(const float4*)&g_pos[bz ? 3 : 1][mm*64 + tx4];
                float bb = b1[mm];
                o.x = acc[r][0] + bb + pv.x; o.y = acc[r][1] + bb + pv.y;
                o.z = acc[r][2] + bb + pv.z; o.w = acc[r][3] + bb + pv.w;
                *(float4*)&g_k[bz][mm*1024 + pt + tx4] = o;
            } else {
                int mm = m - 256;
                float bb = b2[mm];
                o.x = acc[r][0] + bb; o.y = acc[r][1] + bb;
                o.z = acc[r][2] + bb; o.w = acc[r][3] + bb;
                *(float4*)&g_vax[bz][mm*1024 + pt + tx4] = o;
            }
        } else {
            float bb = (bz ? b2 : b1)[m];
            float4 o;
            o.x = acc[r][0] + bb; o.y = acc[r][1] + bb;
            o.z = acc[r][2] + bb; o.w = acc[r][3] + bb;
            int bidx = pt >> 6;
            *(float4*)&g_xx[bz][(bidx*512 + m)*64 + tx4] = o;
        }
    }
}

// ---------------- HMMA GEMM (modes 1, 3, 4) ----------------
// CTA: 256 thr, tile 128(ch) x 128(px); warps 4x2, warp tile 32x64.
// K chunks of 64; smem padded stride 72 bf16 (144B) for conflict-free LDS.
// 3-term bf16 split: AhBh + AhBl + AlBh, fp32 acc.
// MODE 1: W=g_Wvg1 (K=256), B=x          -> g_v / g_g1 (+bias)
// MODE 3: W=g_Wfin[:,0:512], B=relu(v+xx)-> g_g1 = proj + b_proj
// MODE 4: W=g_Wfin[:,512:768], B=g2      -> out = g1 * hsig(acc + b_pw)
#define MM_SMEM (4 * 128 * 72 * 2)   // 73728 B

template <int MODE>
__global__ void __launch_bounds__(256, 1) mm_gemm(
        const float* __restrict__ xin,
        const float* __restrict__ bias0,
        const float* __restrict__ bias1,
        float* __restrict__ outp) {
    extern __shared__ char smem[];
    constexpr int K       = (MODE == 3) ? 512 : 256;
    constexpr int KSTRIDE = (MODE == 1) ? 256 : 768;
    constexpr int KOFF    = (MODE == 4) ? 512 : 0;
    const int tid  = threadIdx.x;
    const int lane = tid & 31;
    const int wid  = tid >> 5;
    const int wm   = wid & 3;          // warp row (32 ch)
    const int wn   = wid >> 2;         // warp col (64 px)
    const int m0   = blockIdx.x * 128;
    const int ptile = blockIdx.y;
    const int b_   = ptile >> 5;
    const int hw0  = (ptile & 31) << 7;
    const int h0   = (ptile & 31) << 1;

    __nv_bfloat16* Ah = (__nv_bfloat16*)smem;      // [128][72]
    __nv_bfloat16* Al = Ah + 128 * 72;
    __nv_bfloat16* Bh = Al + 128 * 72;             // [128 px][72 k]
    __nv_bfloat16* Bl = Bh + 128 * 72;

    const __nv_bfloat16* Wh = (MODE == 1) ? g_Wvg1_h : g_Wfin_h;
    const __nv_bfloat16* Wl = (MODE == 1) ? g_Wvg1_l : g_Wfin_l;

    float acc[2][8][4];
    #pragma unroll
    for (int mf = 0; mf < 2; mf++)
        #pragma unroll
        for (int nf = 0; nf < 8; nf++)
            #pragma unroll
            for (int j = 0; j < 4; j++) acc[mf][nf][j] = 0.f;

    const int kB  = tid >> 2;            // 0..63 (B fill k)
    const int pxq = (tid & 3) << 2;      // 0,4,8,12 (B fill px base)

    for (int kc = 0; kc < K; kc += 64) {
        if (kc) __syncthreads();
        // ---- A fill: 128 x 64 bf16, hi+lo ----
        #pragma unroll
        for (int i = 0; i < 8; i++) {
            int idx = tid + i * 256;
            int m = idx >> 4, k4 = (idx & 15) << 2;
            size_t goff = (size_t)(m0 + m) * KSTRIDE + KOFF + kc + k4;
            *(uint2*)&Ah[m * 72 + k4] = *(const uint2*)&Wh[goff];
            *(uint2*)&Al[m * 72 + k4] = *(const uint2*)&Wl[goff];
        }
        // ---- B fill: 64 k x 128 px, transposed to [px][k], split hi/lo ----
        #pragma unroll
        for (int p = 0; p < 8; p++) {
            int px = pxq + p * 16;
            int kch = kc + kB;
            float4 v4;
            if (MODE == 1) {
                v4 = *(const float4*)&xin[(((size_t)(b_ << 8) + kch) << 12) + hw0 + px];
            } else if (MODE == 3) {
                float4 a4 = *(const float4*)&g_v[(((size_t)(b_*512 + kch)) << 12) + hw0 + px];
                float4 c4 = *(const float4*)&g_xx[1][(b_*512 + kch)*64 + (px & 63)];
                float  xr = g_xx[0][(b_*512 + kch)*64 + h0 + (px >> 6)];
                v4.x = fmaxf(a4.x + c4.x + xr, 0.f);
                v4.y = fmaxf(a4.y + c4.y + xr, 0.f);
                v4.z = fmaxf(a4.z + c4.z + xr, 0.f);
                v4.w = fmaxf(a4.w + c4.w + xr, 0.f);
            } else {
                v4 = *(const float4*)&g_g2[(((size_t)((b_ << 8) + kch)) << 12) + hw0 + px];
            }
            float vv[4] = {v4.x, v4.y, v4.z, v4.w};
            #pragma unroll
            for (int j = 0; j < 4; j++) {
                __nv_bfloat16 h = __float2bfloat16_rn(vv[j]);
                Bh[(px + j) * 72 + kB] = h;
                Bl[(px + j) * 72 + kB] = __float2bfloat16_rn(vv[j] - __bfloat162float(h));
            }
        }
        __syncthreads();
        // ---- compute: 4 k16 steps x 3 terms x (2 mf x 8 nf) mma ----
        #pragma unroll
        for (int kk = 0; kk < 64; kk += 16) {
            uint32_t ah[2][4], al[2][4];
            const int cb = kk + ((lane & 3) << 1);
            #pragma unroll
            for (int mf = 0; mf < 2; mf++) {
                int r = wm * 32 + mf * 16 + (lane >> 2);
                ah[mf][0] = *(const uint32_t*)&Ah[r * 72 + cb];
                ah[mf][1] = *(const uint32_t*)&Ah[(r + 8) * 72 + cb];
                ah[mf][2] = *(const uint32_t*)&Ah[r * 72 + cb + 8];
                ah[mf][3] = *(const uint32_t*)&Ah[(r + 8) * 72 + cb + 8];
                al[mf][0] = *(const uint32_t*)&Al[r * 72 + cb];
                al[mf][1] = *(const uint32_t*)&Al[(r + 8) * 72 + cb];
                al[mf][2] = *(const uint32_t*)&Al[r * 72 + cb + 8];
                al[mf][3] = *(const uint32_t*)&Al[(r + 8) * 72 + cb + 8];
            }
            #pragma unroll
            for (int nf = 0; nf < 8; nf++) {
                int n = wn * 64 + nf * 8 + (lane >> 2);
                uint32_t bh0 = *(const uint32_t*)&Bh[n * 72 + cb];
                uint32_t bh1 = *(const uint32_t*)&Bh[n * 72 + cb + 8];
                uint32_t bl0 = *(const uint32_t*)&Bl[n * 72 + cb];
                uint32_t bl1 = *(const uint32_t*)&Bl[n * 72 + cb + 8];
                #pragma unroll
                for (int mf = 0; mf < 2; mf++) {
                    mma16816(acc[mf][nf], ah[mf], bh0, bh1);
                    mma16816(acc[mf][nf], ah[mf], bl0, bl1);
                    mma16816(acc[mf][nf], al[mf], bh0, bh1);
                }
            }
        }
    }

    // ---- epilogue ----
    #pragma unroll
    for (int mf = 0; mf < 2; mf++) {
        int r0 = m0 + wm * 32 + mf * 16 + (lane >> 2);
        #pragma unroll
        for (int nf = 0; nf < 8; nf++) {
            int pxg = hw0 + wn * 64 + nf * 8 + ((lane & 3) << 1);
            #pragma unroll
            for (int half = 0; half < 2; half++) {
                int m = r0 + half * 8;
                float v0 = acc[mf][nf][half * 2 + 0];
                float v1 = acc[mf][nf][half * 2 + 1];
                if (MODE == 1) {
                    float2 o;
                    if (m < 512) {
                        float bb = bias0[m];
                        o.x = v0 + bb; o.y = v1 + bb;
                        *(float2*)&g_v[(((size_t)(b_*512 + m)) << 12) + pxg] = o;
                    } else {
                        float bb = bias1[m - 512];
                        o.x = v0 + bb; o.y = v1 + bb;
                        *(float2*)&g_g1[(((size_t)((b_ << 8) + m - 512)) << 12) + pxg] = o;
                    }
                } else if (MODE == 3) {
                    float bb = bias0[m];
                    float2 o; o.x = v0 + bb; o.y = v1 + bb;
                    *(float2*)&g_g1[(((size_t)((b_ << 8) + m)) << 12) + pxg] = o;
                } else {
                    float bb = bias1[m];
                    float2 pr = *(const float2*)&g_g1[(((size_t)((b_ << 8) + m)) << 12) + pxg];
                    float2 o;
                    o.x = pr.x * hsig(v0 + bb);
                    o.y = pr.y * hsig(v1 + bb);
                    *(float2*)&outp[(((size_t)((b_ << 8) + m)) << 12) + pxg] = o;
                }
            }
        }
    }
}

// ---------------------------------------------------------------------------
extern "C" void kernel_launch(void* const* d_in, const int* in_sizes, int n_in,
                              void* d_out, int out_size) {
    (void)in_sizes; (void)n_in; (void)out_size;
    P32 ps;
    for (int i = 0; i < 32; i++) ps.p[i] = (const float*)d_in[i];
    const float* x      = ps.p[0];
    const float* bq     = ps.p[3];
    const float* bk     = ps.p[6];
    const float* bv     = ps.p[9];
    const float* b_row  = ps.p[16];
    const float* b_col  = ps.p[19];
    const float* b_proj = ps.p[22];
    const float* b_sc   = ps.p[25];
    const float* b_dw   = ps.p[28];
    const float* b_pw   = ps.p[31];
    float* out = (float*)d_out;

    cudaFuncSetAttribute(mm_gemm<1>, cudaFuncAttributeMaxDynamicSharedMemorySize, MM_SMEM);
    cudaFuncSetAttribute(mm_gemm<3>, cudaFuncAttributeMaxDynamicSharedMemorySize, MM_SMEM);
    cudaFuncSetAttribute(mm_gemm<4>, cudaFuncAttributeMaxDynamicSharedMemorySize, MM_SMEM);

    prep_kernel<<<4489, 256>>>(ps);
    reduce_kernel<<<4096, 256>>>(x);
    gemm_k<0><<<dim3(16, 6, 2), 256>>>(bq, bk, bv);
    attn_kernel<<<256, 64>>>();
    gemm_k<2><<<dim3(16, 4, 2), 256>>>(nullptr, b_row, b_col);
    mm_gemm<1><<<dim3(6, 512), 256, MM_SMEM>>>(x, bv, b_sc, nullptr);
    dw_kernel<<<4096, 256>>>(b_dw);
    mm_gemm<3><<<dim3(2, 512), 256, MM_SMEM>>>(nullptr, b_proj, nullptr, nullptr);
    mm_gemm<4><<<dim3(2, 512), 256, MM_SMEM>>>(nullptr, nullptr, b_pw, out);
}

// round 6
// speedup vs baseline: 1.7533x; 1.0435x over previous
#include <cuda_runtime.h>
#include <cuda_bf16.h>
#include <math.h>
#include <stdint.h>

// ---------------------------------------------------------------------------
// Sea_Attention fused, round 5: HMMA GEMMs with ldmatrix + cp.async pipeline,
// all activations pre-split to bf16 hi/lo at their producers.
//
//   prep      : fold scales; pos tables; bf16 hi/lo split of Wvg1 / Wfin
//   reduce    : row/col means of x; x -> bf16 h/l (g_xbh/g_xbl)
//   gemm_k<0> : axial qkv (fp32 SIMT, tiny)
//   attn      : axial attention
//   gemm_k<2> : w_row/w_col cbn (fp32 SIMT, tiny)
//   mm<1>     : v,g1 = cbn(x); epi: p=relu(v+xx)->bf16 h/l, g1 fp32  [HMMA]
//   dw        : depthwise 3x3 + affine + relu -> g2 bf16 h/l
//   mm<3>     : g1 = proj(p) + b_proj                                [HMMA]
//   mm<4>     : out = g1 * hsig(pw(g2) + b_pw)                       [HMMA]
// ---------------------------------------------------------------------------

#define BB 16

// ---------------- device scratch ----------------
__device__ float g_Wqkv[768*256];
__device__ float g_Wxx[2][512*512];
__device__ __nv_bfloat16 g_Wvg1_h[768*256];
__device__ __nv_bfloat16 g_Wvg1_l[768*256];
__device__ __nv_bfloat16 g_Wfin_h[256*768];
__device__ __nv_bfloat16 g_Wfin_l[256*768];
__device__ float g_wdw[256*9];
__device__ float g_pos[4][128*64];
__device__ float g_xm[2][256*1024];
__device__ float g_q[2][128*1024];
__device__ float g_k[2][128*1024];
__device__ float g_vax[2][512*1024];
__device__ float g_ax[2][512*1024];
__device__ float g_xx[2][BB*512*64];
__device__ float g_g1[(size_t)BB*256*4096];   // gate int.1, then proj results
// bf16 hi/lo activation tensors
__device__ __nv_bfloat16 g_xbh[(size_t)BB*256*4096];
__device__ __nv_bfloat16 g_xbl[(size_t)BB*256*4096];
__device__ __nv_bfloat16 g_pbh[(size_t)BB*512*4096];
__device__ __nv_bfloat16 g_pbl[(size_t)BB*512*4096];
__device__ __nv_bfloat16 g_g2h[(size_t)BB*256*4096];
__device__ __nv_bfloat16 g_g2l[(size_t)BB*256*4096];

struct P32 { const float* p[32]; };

__device__ __forceinline__ float hsig(float x) {
    return fminf(fmaxf(x + 3.0f, 0.0f), 6.0f) * (1.0f / 6.0f);
}

__device__ __forceinline__ uint32_t smem_u32(const void* p) {
    uint32_t a;
    asm("{ .reg .u64 t; cvta.to.shared.u64 t, %1; cvt.u32.u64 %0, t; }" : "=r"(a) : "l"(p));
    return a;
}

__device__ __forceinline__ void mma16816(float (&d)[4], const uint32_t (&a)[4],
                                         uint32_t b0, uint32_t b1) {
    asm volatile(
        "mma.sync.aligned.m16n8k16.row.col.f32.bf16.bf16.f32 "
        "{%0,%1,%2,%3}, {%4,%5,%6,%7}, {%8,%9}, {%0,%1,%2,%3};"
        : "+f"(d[0]), "+f"(d[1]), "+f"(d[2]), "+f"(d[3])
        : "r"(a[0]), "r"(a[1]), "r"(a[2]), "r"(a[3]), "r"(b0), "r"(b1));
}

#define LDSM4(r, a) asm volatile( \
    "ldmatrix.sync.aligned.m8n8.x4.shared.b16 {%0,%1,%2,%3}, [%4];" \
    : "=r"((r)[0]),"=r"((r)[1]),"=r"((r)[2]),"=r"((r)[3]) : "r"(a))
#define LDSM4T(r, a) asm volatile( \
    "ldmatrix.sync.aligned.m8n8.x4.trans.shared.b16 {%0,%1,%2,%3}, [%4];" \
    : "=r"((r)[0]),"=r"((r)[1]),"=r"((r)[2]),"=r"((r)[3]) : "r"(a))
#define CP16(d, s) asm volatile( \
    "cp.async.cg.shared.global [%0], [%1], 16;" :: "r"(d), "l"(s))
#define CP_COMMIT() asm volatile("cp.async.commit_group;")
#define CP_WAIT(n)  asm volatile("cp.async.wait_group %0;" :: "n"(n))

__device__ __forceinline__ uint32_t bpack(float a, float b) {
    __nv_bfloat162 t = __floats2bfloat162_rn(a, b);
    return *reinterpret_cast<uint32_t*>(&t);
}

// ---------------- prep ----------------
__global__ void prep_kernel(P32 ps) {
    int i = blockIdx.x * 256 + threadIdx.x;
    if (i < 196608) {                       // Wqkv fp32
        int r = i >> 8, k = i & 255;
        float v;
        if (r < 128)      v = ps.p[2][r]     * ps.p[1][r*256+k];
        else if (r < 256) v = ps.p[5][r-128] * ps.p[4][(r-128)*256+k];
        else              v = ps.p[8][r-256] * ps.p[7][(r-256)*256+k];
        g_Wqkv[i] = v; return;
    }
    i -= 196608;
    if (i < 196608) {                       // Wvg1 bf16 hi/lo
        int r = i >> 8, k = i & 255;
        float v = (r < 512) ? ps.p[8][r] * ps.p[7][r*256+k]
                            : ps.p[24][r-512] * ps.p[23][(r-512)*256+k];
        __nv_bfloat16 h = __float2bfloat16_rn(v);
        g_Wvg1_h[i] = h;
        g_Wvg1_l[i] = __float2bfloat16_rn(v - __bfloat162float(h));
        return;
    }
    i -= 196608;
    if (i < 262144) { int r = i >> 9; g_Wxx[0][i] = ps.p[15][r] * ps.p[14][i]; return; }
    i -= 262144;
    if (i < 262144) { int r = i >> 9; g_Wxx[1][i] = ps.p[18][r] * ps.p[17][i]; return; }
    i -= 262144;
    if (i < 196608) {                       // Wfin bf16 hi/lo
        int r = i / 768, c = i % 768;
        float v = (c < 512) ? ps.p[21][r] * ps.p[20][r*512+c]
                            : ps.p[30][r] * ps.p[29][r*256+(c-512)];
        __nv_bfloat16 h = __float2bfloat16_rn(v);
        g_Wfin_h[i] = h;
        g_Wfin_l[i] = __float2bfloat16_rn(v - __bfloat162float(h));
        return;
    }
    i -= 196608;
    if (i < 2304) { g_wdw[i] = ps.p[27][i/9] * ps.p[26][i]; return; }
    i -= 2304;
    if (i < 32768) {
        int t = i >> 13, rest = i & 8191;
        int c = rest >> 6, n = rest & 63;
        float coord = 0.25f * (float)n - 0.375f;
        coord = fminf(fmaxf(coord, 0.0f), 15.0f);
        int lo = (int)floorf(coord);
        int hi = min(lo + 1, 15);
        float tf = coord - (float)lo;
        const float* src = ps.p[10 + t];
        g_pos[t][c*64 + n] = src[c*16+lo] * (1.0f - tf) + src[c*16+hi] * tf;
    }
}

// ---------------- reduce + x bf16 split ----------------
__global__ void reduce_kernel(const float* __restrict__ x) {
    int bc = blockIdx.x;
    int b = bc >> 8, c = bc & 255;
    __shared__ float sm[64 * 65];
    int t = threadIdx.x;
    const float* xp = x + (size_t)bc * 4096;
    for (int i = t; i < 4096; i += 256)
        sm[(i >> 6) * 65 + (i & 63)] = xp[i];
    __syncthreads();
    if (t < 64) {
        float s = 0.f;
        #pragma unroll
        for (int w = 0; w < 64; w++) s += sm[t*65 + w];
        g_xm[0][c*1024 + b*64 + t] = s * (1.0f/64.0f);
    } else if (t < 128) {
        int w = t - 64;
        float s = 0.f;
        #pragma unroll
        for (int h = 0; h < 64; h++) s += sm[h*65 + w];
        g_xm[1][c*1024 + b*64 + w] = s * (1.0f/64.0f);
    }
    // bf16 hi/lo split of x
    for (int i = t; i < 4096; i += 256) {
        float v = sm[(i >> 6) * 65 + (i & 63)];
        __nv_bfloat16 h = __float2bfloat16_rn(v);
        g_xbh[(size_t)bc * 4096 + i] = h;
        g_xbl[(size_t)bc * 4096 + i] = __float2bfloat16_rn(v - __bfloat162float(h));
    }
}

// ---------------- axial attention ----------------
__global__ void attn_kernel() {
    int bid = blockIdx.x;
    int br = bid >> 7, b = (bid >> 3) & 15, h = bid & 7;
    __shared__ float qs[16][64], ks[16][64], vs[64][64], ps[64][65];
    int t = threadIdx.x;
    #pragma unroll
    for (int kd = 0; kd < 16; kd++) {
        qs[kd][t] = g_q[br][(h*16+kd)*1024 + b*64 + t];
        ks[kd][t] = g_k[br][(h*16+kd)*1024 + b*64 + t];
    }
    for (int d = 0; d < 64; d++)
        vs[d][t] = g_vax[br][(h*64+d)*1024 + b*64 + t];
    __syncthreads();
    float qreg[16];
    #pragma unroll
    for (int kd = 0; kd < 16; kd++) qreg[kd] = qs[kd][t];
    float mx = -1e30f;
    for (int m = 0; m < 64; m++) {
        float s = 0.f;
        #pragma unroll
        for (int kd = 0; kd < 16; kd++) s = fmaf(qreg[kd], ks[kd][m], s);
        s *= 0.25f;
        ps[t][m] = s;
        mx = fmaxf(mx, s);
    }
    float sum = 0.f;
    for (int m = 0; m < 64; m++) {
        float e = __expf(ps[t][m] - mx);
        ps[t][m] = e;
        sum += e;
    }
    float inv = 1.0f / sum;
    for (int d = 0; d < 64; d++) {
        float o = 0.f;
        for (int m = 0; m < 64; m++) o = fmaf(ps[t][m], vs[d][m], o);
        g_ax[br][(h*64+d)*1024 + b*64 + t] = o * inv;
    }
}

// ---------------- depthwise -> g2 bf16 h/l ----------------
__global__ void dw_kernel(const float* __restrict__ b_dw) {
    int bc = blockIdx.x;
    int c = bc & 255;
    __shared__ float sm[64][65];
    const float* gp = &g_g1[(size_t)bc * 4096];
    int t = threadIdx.x;
    for (int i = t; i < 4096; i += 256) sm[i >> 6][i & 63] = gp[i];
    __syncthreads();
    float w9[9];
    #pragma unroll
    for (int j = 0; j < 9; j++) w9[j] = g_wdw[c*9 + j];
    float bias = b_dw[c];
    for (int i = t; i < 4096; i += 256) {
        int h = i >> 6, w = i & 63;
        float s = 0.f;
        #pragma unroll
        for (int di = 0; di < 3; di++) {
            int hh = h + di - 1;
            if ((unsigned)hh >= 64u) continue;
            #pragma unroll
            for (int dj = 0; dj < 3; dj++) {
                int ww = w + dj - 1;
                if ((unsigned)ww >= 64u) continue;
                s = fmaf(sm[hh][ww], w9[di*3 + dj], s);
            }
        }
        float r = fmaxf(s + bias, 0.0f);
        __nv_bfloat16 hb = __float2bfloat16_rn(r);
        g_g2h[(size_t)bc * 4096 + i] = hb;
        g_g2l[(size_t)bc * 4096 + i] = __float2bfloat16_rn(r - __bfloat162float(hb));
    }
}

// ---------------- small SIMT GEMM (modes 0 & 2) ----------------
#define BM 128
#define BN 64
#define BK 16

__device__ __forceinline__ void rank1(float (&A)[8][4], float4 a0, float4 a1, float4 b) {
    float ar[8] = {a0.x, a0.y, a0.z, a0.w, a1.x, a1.y, a1.z, a1.w};
    #pragma unroll
    for (int r = 0; r < 8; r++) {
        A[r][0] = fmaf(ar[r], b.x, A[r][0]);
        A[r][1] = fmaf(ar[r], b.y, A[r][1]);
        A[r][2] = fmaf(ar[r], b.z, A[r][2]);
        A[r][3] = fmaf(ar[r], b.w, A[r][3]);
    }
}

template <int MODE>
__global__ void __launch_bounds__(256, 2) gemm_k(
        const float* __restrict__ b0, const float* __restrict__ b1,
        const float* __restrict__ b2) {
    constexpr int K = (MODE == 0) ? 256 : 512;
    __shared__ float As[BK][BM + 4];
    __shared__ float Bs[BK][BN + 4];
    const int tid = threadIdx.x;
    const int bx = blockIdx.x, by = blockIdx.y, bz = blockIdx.z;
    const int ty8 = (tid >> 4) << 3;
    const int tx4 = (tid & 15) << 2;
    const int m0 = by * BM;
    const int pt = bx * BN;
    const float* Wm = (MODE == 0) ? g_Wqkv : g_Wxx[bz];
    const int wml = tid >> 1;
    const int wkg = (tid & 1) * 8;
    const int xkk = tid >> 4;
    const int xpl = (tid & 15) << 2;

    float acc[8][4];
    #pragma unroll
    for (int r = 0; r < 8; r++)
        #pragma unroll
        for (int j = 0; j < 4; j++) acc[r][j] = 0.f;

    for (int kt = 0; kt < K; kt += BK) {
        const float* wp = &Wm[(m0 + wml) * K + kt + wkg];
        float4 w0 = *(const float4*)wp;
        float4 w1 = *(const float4*)(wp + 4);
        int k = kt + xkk;
        float4 xv;
        if (MODE == 0) {
            xv = *(const float4*)&g_xm[bz][k*1024 + pt + xpl];
        } else {
            float4 t4 = *(const float4*)&g_ax[bz][k*1024 + pt + xpl];
            xv.x = fmaxf(t4.x, 0.f); xv.y = fmaxf(t4.y, 0.f);
            xv.z = fmaxf(t4.z, 0.f); xv.w = fmaxf(t4.w, 0.f);
        }
        __syncthreads();
        As[wkg+0][wml] = w0.x; As[wkg+1][wml] = w0.y;
        As[wkg+2][wml] = w0.z; As[wkg+3][wml] = w0.w;
        As[wkg+4][wml] = w1.x; As[wkg+5][wml] = w1.y;
        As[wkg+6][wml] = w1.z; As[wkg+7][wml] = w1.w;
        *(float4*)&Bs[xkk][xpl] = xv;
        __syncthreads();
        #pragma unroll
        for (int u = 0; u < BK; u++) {
            float4 a0 = *(const float4*)&As[u][ty8];
            float4 a1 = *(const float4*)&As[u][ty8 + 4];
            float4 bv = *(const float4*)&Bs[u][tx4];
            rank1(acc, a0, a1, bv);
        }
    }

    #pragma unroll
    for (int r = 0; r < 8; r++) {
        int m = m0 + ty8 + r;
        if (MODE == 0) {
            float4 o;
            if (m < 128) {
                float4 pv = *(const float4*)&g_pos[bz ? 2 : 0][m*64 + tx4];
                float bb = b0[m];
                o.x = acc[r][0] + bb + pv.x; o.y = acc[r][1] + bb + pv.y;
                o.z = acc[r][2] + bb + pv.z; o.w = acc[r][3] + bb + pv.w;
                *(float4*)&g_q[bz][m*1024 + pt + tx4] = o;
            } else if (m < 256) {
                int mm = m - 128;
                float4 pv = *(const float4*)&g_pos[bz ? 3 : 1][mm*64 + tx4];
                float bb = b1[mm];
                o.x = acc[r][0] + bb + pv.x; o.y = acc[r][1] + bb + pv.y;
                o.z = acc[r][2] + bb + pv.z; o.w = acc[r][3] + bb + pv.w;
                *(float4*)&g_k[bz][mm*1024 + pt + tx4] = o;
            } else {
                int mm = m - 256;
                float bb = b2[mm];
                o.x = acc[r][0] + bb; o.y = acc[r][1] + bb;
                o.z = acc[r][2] + bb; o.w = acc[r][3] + bb;
                *(float4*)&g_vax[bz][mm*1024 + pt + tx4] = o;
            }
        } else {
            float bb = (bz ? b2 : b1)[m];
            float4 o;
            o.x = acc[r][0] + bb; o.y = acc[r][1] + bb;
            o.z = acc[r][2] + bb; o.w = acc[r][3] + bb;
            int bidx = pt >> 6;
            *(float4*)&g_xx[bz][(bidx*512 + m)*64 + tx4] = o;
        }
    }
}

// ---------------- HMMA GEMM (modes 1, 3, 4) ----------------
// CTA 256 thr, tile 128(ch) x 128(px); warps 4x2, warp tile 32x64.
// Double-buffered cp.async; smem: A[128][72] h+l, B[64][136] h+l per stage.
// Fragments via ldmatrix (A) / ldmatrix.trans (B).
// Stage byte layout: Ah 0 | Al 18432 | Bh 36864 | Bl 54272 ; stride 71680.
#define MM_SMEM (2 * 71680)

template <int MODE>
__global__ void __launch_bounds__(256) mm_gemm(
        const float* __restrict__ bias0,
        const float* __restrict__ bias1,
        float* __restrict__ outp) {
    extern __shared__ char smem[];
    constexpr int K       = (MODE == 3) ? 512 : 256;
    constexpr int NC      = K / 64;
    constexpr int KSTRIDE = (MODE == 1) ? 256 : 768;
    constexpr int KOFF    = (MODE == 4) ? 512 : 0;
    constexpr int CH      = (MODE == 3) ? 512 : 256;   // B-tensor channel count
    const int tid = threadIdx.x, lane = tid & 31, wid = tid >> 5;
    const int wm = wid & 3, wn = wid >> 2;
    const int m0 = blockIdx.x * 128;
    const int pt = blockIdx.y;
    const int b_ = pt >> 5;
    const int hw0 = (pt & 31) << 7;

    const uint32_t sb = smem_u32(smem);
    const __nv_bfloat16* Wh  = (MODE == 1) ? g_Wvg1_h : g_Wfin_h;
    const __nv_bfloat16* Wl  = (MODE == 1) ? g_Wvg1_l : g_Wfin_l;
    const __nv_bfloat16* Bhg = (MODE == 1) ? g_xbh : (MODE == 3) ? g_pbh : g_g2h;
    const __nv_bfloat16* Blg = (MODE == 1) ? g_xbl : (MODE == 3) ? g_pbl : g_g2l;

    float acc[2][8][4];
    #pragma unroll
    for (int mf = 0; mf < 2; mf++)
        #pragma unroll
        for (int nf = 0; nf < 8; nf++)
            #pragma unroll
            for (int j = 0; j < 4; j++) acc[mf][nf][j] = 0.f;

    auto FILL = [&](int c) {
        const uint32_t st = sb + (uint32_t)(c & 1) * 71680u;
        const int kc = c * 64;
        #pragma unroll
        for (int i = 0; i < 4; i++) {          // A: 128x64 bf16 h+l
            int idx = tid + i * 256;
            int m = idx >> 3, k8 = (idx & 7) << 3;
            size_t g = (size_t)(m0 + m) * KSTRIDE + KOFF + kc + k8;
            uint32_t d = st + (uint32_t)(m * 144 + k8 * 2);
            CP16(d, Wh + g);
            CP16(d + 18432u, Wl + g);
        }
        #pragma unroll
        for (int i = 0; i < 4; i++) {          // B: 64k x 128px bf16 h+l
            int idx = tid + i * 256;
            int k = idx >> 4, px8 = (idx & 15) << 3;
            size_t g = (((size_t)(b_ * CH + kc + k)) << 12) + hw0 + px8;
            uint32_t d = st + 36864u + (uint32_t)(k * 272 + px8 * 2);
            CP16(d, Bhg + g);
            CP16(d + 17408u, Blg + g);
        }
    };

    FILL(0); CP_COMMIT();
    for (int c = 0; c < NC; c++) {
        if (c + 1 < NC) { FILL(c + 1); CP_COMMIT(); CP_WAIT(1); }
        else            { CP_WAIT(0); }
        __syncthreads();
        const uint32_t st = sb + (uint32_t)(c & 1) * 71680u;
        #pragma unroll
        for (int kk = 0; kk < 64; kk += 16) {
            uint32_t ah[2][4], al[2][4];
            uint32_t aoff = st + (uint32_t)(((wm * 32 + (lane & 15)) * 72
                              + kk + ((lane >> 4) << 3)) * 2);
            LDSM4(ah[0], aoff);
            LDSM4(ah[1], aoff + 16u * 144u);
            LDSM4(al[0], aoff + 18432u);
            LDSM4(al[1], aoff + 18432u + 16u * 144u);
            #pragma unroll
            for (int np = 0; np < 4; np++) {
                uint32_t bh[4], bl[4];
                uint32_t boff = st + 36864u + (uint32_t)(
                    ((kk + (lane & 7) + (((lane >> 3) & 1) << 3)) * 136
                     + wn * 64 + np * 16 + ((lane >> 4) << 3)) * 2);
                LDSM4T(bh, boff);
                LDSM4T(bl, boff + 17408u);
                #pragma unroll
                for (int mf = 0; mf < 2; mf++) {
                    mma16816(acc[mf][2*np],   ah[mf], bh[0], bh[1]);
                    mma16816(acc[mf][2*np],   ah[mf], bl[0], bl[1]);
                    mma16816(acc[mf][2*np],   al[mf], bh[0], bh[1]);
                    mma16816(acc[mf][2*np+1], ah[mf], bh[2], bh[3]);
                    mma16816(acc[mf][2*np+1], ah[mf], bl[2], bl[3]);
                    mma16816(acc[mf][2*np+1], al[mf], bh[2], bh[3]);
                }
            }
        }
        __syncthreads();
    }

    // ---- epilogue ----
    #pragma unroll
    for (int mf = 0; mf < 2; mf++) {
        int r0 = m0 + wm * 32 + mf * 16 + (lane >> 2);
        #pragma unroll
        for (int nf = 0; nf < 8; nf++) {
            int pxg = hw0 + wn * 64 + nf * 8 + ((lane & 3) << 1);
            #pragma unroll
            for (int half = 0; half < 2; half++) {
                int m = r0 + half * 8;
                float v0 = acc[mf][nf][half * 2 + 0];
                float v1 = acc[mf][nf][half * 2 + 1];
                if (MODE == 1) {
                    if (m < 512) {
                        float bb = bias0[m];
                        int hh = pxg >> 6, ww = pxg & 63;
                        float xr = g_xx[0][(b_*512 + m)*64 + hh];
                        float2 xc = *(const float2*)&g_xx[1][(b_*512 + m)*64 + ww];
                        float p0 = fmaxf(v0 + bb + xr + xc.x, 0.f);
                        float p1 = fmaxf(v1 + bb + xr + xc.y, 0.f);
                        float h0 = __bfloat162float(__float2bfloat16_rn(p0));
                        float h1 = __bfloat162float(__float2bfloat16_rn(p1));
                        size_t o = (((size_t)(b_*512 + m)) << 12) + pxg;
                        *(uint32_t*)&g_pbh[o] = bpack(p0, p1);
                        *(uint32_t*)&g_pbl[o] = bpack(p0 - h0, p1 - h1);
                    } else {
                        float bb = bias1[m - 512];
                        float2 o2 = {v0 + bb, v1 + bb};
                        *(float2*)&g_g1[(((size_t)((b_ << 8) + m - 512)) << 12) + pxg] = o2;
                    }
                } else if (MODE == 3) {
                    float bb = bias0[m];
                    float2 o2 = {v0 + bb, v1 + bb};
                    *(float2*)&g_g1[(((size_t)((b_ << 8) + m)) << 12) + pxg] = o2;
                } else {
                    float bb = bias1[m];
                    float2 pr = *(const float2*)&g_g1[(((size_t)((b_ << 8) + m)) << 12) + pxg];
                    float2 o2 = {pr.x * hsig(v0 + bb), pr.y * hsig(v1 + bb)};
                    *(float2*)&outp[(((size_t)((b_ << 8) + m)) << 12) + pxg] = o2;
                }
            }
        }
    }
}

// ---------------------------------------------------------------------------
extern "C" void kernel_launch(void* const* d_in, const int* in_sizes, int n_in,
                              void* d_out, int out_size) {
    (void)in_sizes; (void)n_in; (void)out_size;
    P32 ps;
    for (int i = 0; i < 32; i++) ps.p[i] = (const float*)d_in[i];
    const float* x      = ps.p[0];
    const float* bq     = ps.p[3];
    const float* bk     = ps.p[6];
    const float* bv     = ps.p[9];
    const float* b_row  = ps.p[16];
    const float* b_col  = ps.p[19];
    const float* b_proj = ps.p[22];
    const float* b_sc   = ps.p[25];
    const float* b_dw   = ps.p[28];
    const float* b_pw   = ps.p[31];
    float* out = (float*)d_out;

    cudaFuncSetAttribute(mm_gemm<1>, cudaFuncAttributeMaxDynamicSharedMemorySize, MM_SMEM);
    cudaFuncSetAttribute(mm_gemm<3>, cudaFuncAttributeMaxDynamicSharedMemorySize, MM_SMEM);
    cudaFuncSetAttribute(mm_gemm<4>, cudaFuncAttributeMaxDynamicSharedMemorySize, MM_SMEM);

    prep_kernel<<<4489, 256>>>(ps);
    reduce_kernel<<<4096, 256>>>(x);
    gemm_k<0><<<dim3(16, 6, 2), 256>>>(bq, bk, bv);
    attn_kernel<<<256, 64>>>();
    gemm_k<2><<<dim3(16, 4, 2), 256>>>(nullptr, b_row, b_col);
    mm_gemm<1><<<dim3(6, 512), 256, MM_SMEM>>>(bv, b_sc, nullptr);
    dw_kernel<<<4096, 256>>>(b_dw);
    mm_gemm<3><<<dim3(2, 512), 256, MM_SMEM>>>(b_proj, nullptr, nullptr);
    mm_gemm<4><<<dim3(2, 512), 256, MM_SMEM>>>(nullptr, b_pw, out);
}

// round 8
// speedup vs baseline: 2.6370x; 1.5040x over previous
#include <cuda_runtime.h>
#include <cuda_bf16.h>
#include <cuda_fp16.h>
#include <math.h>
#include <stdint.h>

// ---------------------------------------------------------------------------
// Sea_Attention fused, round 6: HMMA GEMMs in fp16 2-term split
// (weights hi/lo fp16, activations single fp16) -> 2/3 the MMA instructions.
// ---------------------------------------------------------------------------

#define BB 16

// ---------------- device scratch ----------------
__device__ float g_Wqkv[768*256];
__device__ float g_Wxx[2][512*512];
__device__ __half g_Wvg1_h[768*256];
__device__ __half g_Wvg1_l[768*256];
__device__ __half g_Wfin_h[256*768];
__device__ __half g_Wfin_l[256*768];
__device__ float g_wdw[256*9];
__device__ float g_pos[4][128*64];
__device__ float g_xm[2][256*1024];
__device__ float g_q[2][128*1024];
__device__ float g_k[2][128*1024];
__device__ float g_vax[2][512*1024];
__device__ float g_ax[2][512*1024];
__device__ float g_xx[2][BB*512*64];
__device__ float g_g1[(size_t)BB*256*4096];   // gate int.1, then proj results
// fp16 activation tensors
__device__ __half g_xh[(size_t)BB*256*4096];
__device__ __half g_pb[(size_t)BB*512*4096];
__device__ __half g_g2b[(size_t)BB*256*4096];

struct P32 { const float* p[32]; };

__device__ __forceinline__ float hsig(float x) {
    return fminf(fmaxf(x + 3.0f, 0.0f), 6.0f) * (1.0f / 6.0f);
}

__device__ __forceinline__ uint32_t smem_u32(const void* p) {
    uint32_t a;
    asm("{ .reg .u64 t; cvta.to.shared.u64 t, %1; cvt.u32.u64 %0, t; }" : "=r"(a) : "l"(p));
    return a;
}

__device__ __forceinline__ void mma16816(float (&d)[4], const uint32_t (&a)[4],
                                         uint32_t b0, uint32_t b1) {
    asm volatile(
        "mma.sync.aligned.m16n8k16.row.col.f32.f16.f16.f32 "
        "{%0,%1,%2,%3}, {%4,%5,%6,%7}, {%8,%9}, {%0,%1,%2,%3};"
        : "+f"(d[0]), "+f"(d[1]), "+f"(d[2]), "+f"(d[3])
        : "r"(a[0]), "r"(a[1]), "r"(a[2]), "r"(a[3]), "r"(b0), "r"(b1));
}

#define LDSM4(r, a) asm volatile( \
    "ldmatrix.sync.aligned.m8n8.x4.shared.b16 {%0,%1,%2,%3}, [%4];" \
    : "=r"((r)[0]),"=r"((r)[1]),"=r"((r)[2]),"=r"((r)[3]) : "r"(a))
#define LDSM4T(r, a) asm volatile( \
    "ldmatrix.sync.aligned.m8n8.x4.trans.shared.b16 {%0,%1,%2,%3}, [%4];" \
    : "=r"((r)[0]),"=r"((r)[1]),"=r"((r)[2]),"=r"((r)[3]) : "r"(a))
#define CP16(d, s) asm volatile( \
    "cp.async.cg.shared.global [%0], [%1], 16;" :: "r"(d), "l"(s))
#define CP_COMMIT() asm volatile("cp.async.commit_group;")
#define CP_WAIT(n)  asm volatile("cp.async.wait_group %0;" :: "n"(n))

__device__ __forceinline__ uint32_t hpack(float a, float b) {
    __half2 t = __floats2half2_rn(a, b);
    return *reinterpret_cast<uint32_t*>(&t);
}

// ---------------- prep ----------------
__global__ void prep_kernel(P32 ps) {
    int i = blockIdx.x * 256 + threadIdx.x;
    if (i < 196608) {                       // Wqkv fp32
        int r = i >> 8, k = i & 255;
        float v;
        if (r < 128)      v = ps.p[2][r]     * ps.p[1][r*256+k];
        else if (r < 256) v = ps.p[5][r-128] * ps.p[4][(r-128)*256+k];
        else              v = ps.p[8][r-256] * ps.p[7][(r-256)*256+k];
        g_Wqkv[i] = v; return;
    }
    i -= 196608;
    if (i < 196608) {                       // Wvg1 fp16 hi/lo
        int r = i >> 8, k = i & 255;
        float v = (r < 512) ? ps.p[8][r] * ps.p[7][r*256+k]
                            : ps.p[24][r-512] * ps.p[23][(r-512)*256+k];
        __half h = __float2half_rn(v);
        g_Wvg1_h[i] = h;
        g_Wvg1_l[i] = __float2half_rn(v - __half2float(h));
        return;
    }
    i -= 196608;
    if (i < 262144) { int r = i >> 9; g_Wxx[0][i] = ps.p[15][r] * ps.p[14][i]; return; }
    i -= 262144;
    if (i < 262144) { int r = i >> 9; g_Wxx[1][i] = ps.p[18][r] * ps.p[17][i]; return; }
    i -= 262144;
    if (i < 196608) {                       // Wfin fp16 hi/lo
        int r = i / 768, c = i % 768;
        float v = (c < 512) ? ps.p[21][r] * ps.p[20][r*512+c]
                            : ps.p[30][r] * ps.p[29][r*256+(c-512)];
        __half h = __float2half_rn(v);
        g_Wfin_h[i] = h;
        g_Wfin_l[i] = __float2half_rn(v - __half2float(h));
        return;
    }
    i -= 196608;
    if (i < 2304) { g_wdw[i] = ps.p[27][i/9] * ps.p[26][i]; return; }
    i -= 2304;
    if (i < 32768) {
        int t = i >> 13, rest = i & 8191;
        int c = rest >> 6, n = rest & 63;
        float coord = 0.25f * (float)n - 0.375f;
        coord = fminf(fmaxf(coord, 0.0f), 15.0f);
        int lo = (int)floorf(coord);
        int hi = min(lo + 1, 15);
        float tf = coord - (float)lo;
        const float* src = ps.p[10 + t];
        g_pos[t][c*64 + n] = src[c*16+lo] * (1.0f - tf) + src[c*16+hi] * tf;
    }
}

// ---------------- reduce + x fp16 ----------------
__global__ void reduce_kernel(const float* __restrict__ x) {
    int bc = blockIdx.x;
    int b = bc >> 8, c = bc & 255;
    __shared__ float sm[64 * 65];
    int t = threadIdx.x;
    const float* xp = x + (size_t)bc * 4096;
    for (int i = t; i < 4096; i += 256)
        sm[(i >> 6) * 65 + (i & 63)] = xp[i];
    __syncthreads();
    if (t < 64) {
        float s = 0.f;
        #pragma unroll
        for (int w = 0; w < 64; w++) s += sm[t*65 + w];
        g_xm[0][c*1024 + b*64 + t] = s * (1.0f/64.0f);
    } else if (t < 128) {
        int w = t - 64;
        float s = 0.f;
        #pragma unroll
        for (int h = 0; h < 64; h++) s += sm[h*65 + w];
        g_xm[1][c*1024 + b*64 + w] = s * (1.0f/64.0f);
    }
    for (int i = t; i < 4096; i += 256)
        g_xh[(size_t)bc * 4096 + i] = __float2half_rn(sm[(i >> 6) * 65 + (i & 63)]);
}

// ---------------- axial attention ----------------
__global__ void attn_kernel() {
    int bid = blockIdx.x;
    int br = bid >> 7, b = (bid >> 3) & 15, h = bid & 7;
    __shared__ float qs[16][64], ks[16][64], vs[64][64], ps[64][65];
    int t = threadIdx.x;
    #pragma unroll
    for (int kd = 0; kd < 16; kd++) {
        qs[kd][t] = g_q[br][(h*16+kd)*1024 + b*64 + t];
        ks[kd][t] = g_k[br][(h*16+kd)*1024 + b*64 + t];
    }
    for (int d = 0; d < 64; d++)
        vs[d][t] = g_vax[br][(h*64+d)*1024 + b*64 + t];
    __syncthreads();
    float qreg[16];
    #pragma unroll
    for (int kd = 0; kd < 16; kd++) qreg[kd] = qs[kd][t];
    float mx = -1e30f;
    for (int m = 0; m < 64; m++) {
        float s = 0.f;
        #pragma unroll
        for (int kd = 0; kd < 16; kd++) s = fmaf(qreg[kd], ks[kd][m], s);
        s *= 0.25f;
        ps[t][m] = s;
        mx = fmaxf(mx, s);
    }
    float sum = 0.f;
    for (int m = 0; m < 64; m++) {
        float e = __expf(ps[t][m] - mx);
        ps[t][m] = e;
        sum += e;
    }
    float inv = 1.0f / sum;
    for (int d = 0; d < 64; d++) {
        float o = 0.f;
        for (int m = 0; m < 64; m++) o = fmaf(ps[t][m], vs[d][m], o);
        g_ax[br][(h*64+d)*1024 + b*64 + t] = o * inv;
    }
}

// ---------------- depthwise -> g2 fp16 ----------------
__global__ void dw_kernel(const float* __restrict__ b_dw) {
    int bc = blockIdx.x;
    int c = bc & 255;
    __shared__ float sm[64][65];
    const float* gp = &g_g1[(size_t)bc * 4096];
    int t = threadIdx.x;
    for (int i = t; i < 4096; i += 256) sm[i >> 6][i & 63] = gp[i];
    __syncthreads();
    float w9[9];
    #pragma unroll
    for (int j = 0; j < 9; j++) w9[j] = g_wdw[c*9 + j];
    float bias = b_dw[c];
    for (int i = t; i < 4096; i += 256) {
        int h = i >> 6, w = i & 63;
        float s = 0.f;
        #pragma unroll
        for (int di = 0; di < 3; di++) {
            int hh = h + di - 1;
            if ((unsigned)hh >= 64u) continue;
            #pragma unroll
            for (int dj = 0; dj < 3; dj++) {
                int ww = w + dj - 1;
                if ((unsigned)ww >= 64u) continue;
                s = fmaf(sm[hh][ww], w9[di*3 + dj], s);
            }
        }
        g_g2b[(size_t)bc * 4096 + i] = __float2half_rn(fmaxf(s + bias, 0.0f));
    }
}

// ---------------- small SIMT GEMM (modes 0 & 2) ----------------
#define BM 128
#define BN 64
#define BK 16

__device__ __forceinline__ void rank1(float (&A)[8][4], float4 a0, float4 a1, float4 b) {
    float ar[8] = {a0.x, a0.y, a0.z, a0.w, a1.x, a1.y, a1.z, a1.w};
    #pragma unroll
    for (int r = 0; r < 8; r++) {
        A[r][0] = fmaf(ar[r], b.x, A[r][0]);
        A[r][1] = fmaf(ar[r], b.y, A[r][1]);
        A[r][2] = fmaf(ar[r], b.z, A[r][2]);
        A[r][3] = fmaf(ar[r], b.w, A[r][3]);
    }
}

template <int MODE>
__global__ void __launch_bounds__(256, 2) gemm_k(
        const float* __restrict__ b0, const float* __restrict__ b1,
        const float* __restrict__ b2) {
    constexpr int K = (MODE == 0) ? 256 : 512;
    __shared__ float As[BK][BM + 4];
    __shared__ float Bs[BK][BN + 4];
    const int tid = threadIdx.x;
    const int bx = blockIdx.x, by = blockIdx.y, bz = blockIdx.z;
    const int ty8 = (tid >> 4) << 3;
    const int tx4 = (tid & 15) << 2;
    const int m0 = by * BM;
    const int pt = bx * BN;
    const float* Wm = (MODE == 0) ? g_Wqkv : g_Wxx[bz];
    const int wml = tid >> 1;
    const int wkg = (tid & 1) * 8;
    const int xkk = tid >> 4;
    const int xpl = (tid & 15) << 2;

    float acc[8][4];
    #pragma unroll
    for (int r = 0; r < 8; r++)
        #pragma unroll
        for (int j = 0; j < 4; j++) acc[r][j] = 0.f;

    for (int kt = 0; kt < K; kt += BK) {
        const float* wp = &Wm[(m0 + wml) * K + kt + wkg];
        float4 w0 = *(const float4*)wp;
        float4 w1 = *(const float4*)(wp + 4);
        int k = kt + xkk;
        float4 xv;
        if (MODE == 0) {
            xv = *(const float4*)&g_xm[bz][k*1024 + pt + xpl];
        } else {
            float4 t4 = *(const float4*)&g_ax[bz][k*1024 + pt + xpl];
            xv.x = fmaxf(t4.x, 0.f); xv.y = fmaxf(t4.y, 0.f);
            xv.z = fmaxf(t4.z, 0.f); xv.w = fmaxf(t4.w, 0.f);
        }
        __syncthreads();
        As[wkg+0][wml] = w0.x; As[wkg+1][wml] = w0.y;
        As[wkg+2][wml] = w0.z; As[wkg+3][wml] = w0.w;
        As[wkg+4][wml] = w1.x; As[wkg+5][wml] = w1.y;
        As[wkg+6][wml] = w1.z; As[wkg+7][wml] = w1.w;
        *(float4*)&Bs[xkk][xpl] = xv;
        __syncthreads();
        #pragma unroll
        for (int u = 0; u < BK; u++) {
            float4 a0 = *(const float4*)&As[u][ty8];
            float4 a1 = *(const float4*)&As[u][ty8 + 4];
            float4 bv = *(const float4*)&Bs[u][tx4];
            rank1(acc, a0, a1, bv);
        }
    }

    #pragma unroll
    for (int r = 0; r < 8; r++) {
        int m = m0 + ty8 + r;
        if (MODE == 0) {
            float4 o;
            if (m < 128) {
                float4 pv = *(const float4*)&g_pos[bz ? 2 : 0][m*64 + tx4];
                float bb = b0[m];
                o.x = acc[r][0] + bb + pv.x; o.y = acc[r][1] + bb + pv.y;
                o.z = acc[r][2] + bb + pv.z; o.w = acc[r][3] + bb + pv.w;
                *(float4*)&g_q[bz][m*1024 + pt + tx4] = o;
            } else if (m < 256) {
                int mm = m - 128;
                float4 pv = *(const float4*)&g_pos[bz ? 3 : 1][mm*64 + tx4];
                float bb = b1[mm];
                o.x = acc[r][0] + bb + pv.x; o.y = acc[r][1] + bb + pv.y;
                o.z = acc[r][2] + bb + pv.z; o.w = acc[r][3] + bb + pv.w;
                *(float4*)&g_k[bz][mm*1024 + pt + tx4] = o;
            } else {
                int mm = m - 256;
                float bb = b2[mm];
                o.x = acc[r][0] + bb; o.y = acc[r][1] + bb;
                o.z = acc[r][2] + bb; o.w = acc[r][3] + bb;
                *(float4*)&g_vax[bz][mm*1024 + pt + tx4] = o;
            }
        } else {
            float bb = (bz ? b2 : b1)[m];
            float4 o;
            o.x = acc[r][0] + bb; o.y = acc[r][1] + bb;
            o.z = acc[r][2] + bb; o.w = acc[r][3] + bb;
            int bidx = pt >> 6;
            *(float4*)&g_xx[bz][(bidx*512 + m)*64 + tx4] = o;
        }
    }
}

// ---------------- HMMA GEMM (modes 1, 3, 4) ----------------
// CTA 256 thr, tile 128(ch) x 128(px); warps 4x2, warp tile 32x64.
// fp16 2-term split: (Wh + Wl) x B_fp16, fp32 acc.
// Stage layout: Ah 0 (128x72, 144B stride) | Al 18432 | B 36864 (64x136, 272B)
// Stage stride 54272 B; 2 stages.
#define MM_SMEM (2 * 54272)

template <int MODE>
__global__ void __launch_bounds__(256) mm_gemm(
        const float* __restrict__ bias0,
        const float* __restrict__ bias1,
        float* __restrict__ outp) {
    extern __shared__ char smem[];
    constexpr int K       = (MODE == 3) ? 512 : 256;
    constexpr int NC      = K / 64;
    constexpr int KSTRIDE = (MODE == 1) ? 256 : 768;
    constexpr int KOFF    = (MODE == 4) ? 512 : 0;
    constexpr int CH      = (MODE == 3) ? 512 : 256;
    const int tid = threadIdx.x, lane = tid & 31, wid = tid >> 5;
    const int wm = wid & 3, wn = wid >> 2;
    const int m0 = blockIdx.x * 128;
    const int pt = blockIdx.y;
    const int b_ = pt >> 5;
    const int hw0 = (pt & 31) << 7;

    const uint32_t sb = smem_u32(smem);
    const __half* Wh  = (MODE == 1) ? g_Wvg1_h : g_Wfin_h;
    const __half* Wl  = (MODE == 1) ? g_Wvg1_l : g_Wfin_l;
    const __half* Bg  = (MODE == 1) ? g_xh : (MODE == 3) ? g_pb : g_g2b;

    float acc[2][8][4];
    #pragma unroll
    for (int mf = 0; mf < 2; mf++)
        #pragma unroll
        for (int nf = 0; nf < 8; nf++)
            #pragma unroll
            for (int j = 0; j < 4; j++) acc[mf][nf][j] = 0.f;

    auto FILL = [&](int c) {
        const uint32_t st = sb + (uint32_t)(c & 1) * 54272u;
        const int kc = c * 64;
        #pragma unroll
        for (int i = 0; i < 4; i++) {          // A: 128x64 fp16 h+l
            int idx = tid + i * 256;
            int m = idx >> 3, k8 = (idx & 7) << 3;
            size_t g = (size_t)(m0 + m) * KSTRIDE + KOFF + kc + k8;
            uint32_t d = st + (uint32_t)(m * 144 + k8 * 2);
            CP16(d, Wh + g);
            CP16(d + 18432u, Wl + g);
        }
        #pragma unroll
        for (int i = 0; i < 4; i++) {          // B: 64k x 128px fp16
            int idx = tid + i * 256;
            int k = idx >> 4, px8 = (idx & 15) << 3;
            size_t g = (((size_t)(b_ * CH + kc + k)) << 12) + hw0 + px8;
            uint32_t d = st + 36864u + (uint32_t)(k * 272 + px8 * 2);
            CP16(d, Bg + g);
        }
    };

    FILL(0); CP_COMMIT();
    for (int c = 0; c < NC; c++) {
        if (c + 1 < NC) { FILL(c + 1); CP_COMMIT(); CP_WAIT(1); }
        else            { CP_WAIT(0); }
        __syncthreads();
        const uint32_t st = sb + (uint32_t)(c & 1) * 54272u;
        #pragma unroll
        for (int kk = 0; kk < 64; kk += 16) {
            uint32_t ah[2][4], al[2][4];
            uint32_t aoff = st + (uint32_t)(((wm * 32 + (lane & 15)) * 72
                              + kk + ((lane >> 4) << 3)) * 2);
            LDSM4(ah[0], aoff);
            LDSM4(ah[1], aoff + 16u * 144u);
            LDSM4(al[0], aoff + 18432u);
            LDSM4(al[1], aoff + 18432u + 16u * 144u);
            #pragma unroll
            for (int np = 0; np < 4; np++) {
                uint32_t bh[4];
                uint32_t boff = st + 36864u + (uint32_t)(
                    ((kk + (lane & 7) + (((lane >> 3) & 1) << 3)) * 136
                     + wn * 64 + np * 16 + ((lane >> 4) << 3)) * 2);
                LDSM4T(bh, boff);
                #pragma unroll
                for (int mf = 0; mf < 2; mf++) {
                    mma16816(acc[mf][2*np],   ah[mf], bh[0], bh[1]);
                    mma16816(acc[mf][2*np],   al[mf], bh[0], bh[1]);
                    mma16816(acc[mf][2*np+1], ah[mf], bh[2], bh[3]);
                    mma16816(acc[mf][2*np+1], al[mf], bh[2], bh[3]);
                }
            }
        }
        __syncthreads();
    }

    // ---- epilogue ----
    #pragma unroll
    for (int mf = 0; mf < 2; mf++) {
        int r0 = m0 + wm * 32 + mf * 16 + (lane >> 2);
        #pragma unroll
        for (int nf = 0; nf < 8; nf++) {
            int pxg = hw0 + wn * 64 + nf * 8 + ((lane & 3) << 1);
            #pragma unroll
            for (int half = 0; half < 2; half++) {
                int m = r0 + half * 8;
                float v0 = acc[mf][nf][half * 2 + 0];
                float v1 = acc[mf][nf][half * 2 + 1];
                if (MODE == 1) {
                    if (m < 512) {
                        float bb = bias0[m];
                        int hh = pxg >> 6, ww = pxg & 63;
                        float xr = g_xx[0][(b_*512 + m)*64 + hh];
                        float2 xc = *(const float2*)&g_xx[1][(b_*512 + m)*64 + ww];
                        float p0 = fmaxf(v0 + bb + xr + xc.x, 0.f);
                        float p1 = fmaxf(v1 + bb + xr + xc.y, 0.f);
                        size_t o = (((size_t)(b_*512 + m)) << 12) + pxg;
                        *(uint32_t*)&g_pb[o] = hpack(p0, p1);
                    } else {
                        float bb = bias1[m - 512];
                        float2 o2 = {v0 + bb, v1 + bb};
                        *(float2*)&g_g1[(((size_t)((b_ << 8) + m - 512)) << 12) + pxg] = o2;
                    }
                } else if (MODE == 3) {
                    float bb = bias0[m];
                    float2 o2 = {v0 + bb, v1 + bb};
                    *(float2*)&g_g1[(((size_t)((b_ << 8) + m)) << 12) + pxg] = o2;
                } else {
                    float bb = bias1[m];
                    float2 pr = *(const float2*)&g_g1[(((size_t)((b_ << 8) + m)) << 12) + pxg];
                    float2 o2 = {pr.x * hsig(v0 + bb), pr.y * hsig(v1 + bb)};
                    *(float2*)&outp[(((size_t)((b_ << 8) + m)) << 12) + pxg] = o2;
                }
            }
        }
    }
}

// ---------------------------------------------------------------------------
extern "C" void kernel_launch(void* const* d_in, const int* in_sizes, int n_in,
                              void* d_out, int out_size) {
    (void)in_sizes; (void)n_in; (void)out_size;
    P32 ps;
    for (int i = 0; i < 32; i++) ps.p[i] = (const float*)d_in[i];
    const float* x      = ps.p[0];
    const float* bq     = ps.p[3];
    const float* bk     = ps.p[6];
    const float* bv     = ps.p[9];
    const float* b_row  = ps.p[16];
    const float* b_col  = ps.p[19];
    const float* b_proj = ps.p[22];
    const float* b_sc   = ps.p[25];
    const float* b_dw   = ps.p[28];
    const float* b_pw   = ps.p[31];
    float* out = (float*)d_out;

    cudaFuncSetAttribute(mm_gemm<1>, cudaFuncAttributeMaxDynamicSharedMemorySize, MM_SMEM);
    cudaFuncSetAttribute(mm_gemm<3>, cudaFuncAttributeMaxDynamicSharedMemorySize, MM_SMEM);
    cudaFuncSetAttribute(mm_gemm<4>, cudaFuncAttributeMaxDynamicSharedMemorySize, MM_SMEM);

    prep_kernel<<<4489, 256>>>(ps);
    reduce_kernel<<<4096, 256>>>(x);
    gemm_k<0><<<dim3(16, 6, 2), 256>>>(bq, bk, bv);
    attn_kernel<<<256, 64>>>();
    gemm_k<2><<<dim3(16, 4, 2), 256>>>(nullptr, b_row, b_col);
    mm_gemm<1><<<dim3(6, 512), 256, MM_SMEM>>>(bv, b_sc, nullptr);
    dw_kernel<<<4096, 256>>>(b_dw);
    mm_gemm<3><<<dim3(2, 512), 256, MM_SMEM>>>(b_proj, nullptr, nullptr);
    mm_gemm<4><<<dim3(2, 512), 256, MM_SMEM>>>(nullptr, b_pw, out);
}

// round 9
// speedup vs baseline: 3.2236x; 1.2225x over previous
#include <cuda_runtime.h>
#include <cuda_bf16.h>
#include <cuda_fp16.h>
#include <math.h>
#include <stdint.h>

// ---------------------------------------------------------------------------
// Sea_Attention fused, round 8: HMMA GEMMs in pure fp16 (1-term), fp32 acc.
// Calibrated model: mm kernels are MMA-issue-bound; time ~ MMA count.
// ---------------------------------------------------------------------------

#define BB 16

// ---------------- device scratch ----------------
__device__ float g_Wqkv[768*256];
__device__ float g_Wxx[2][512*512];
__device__ __half g_Wvg1_h[768*256];
__device__ __half g_Wfin_h[256*768];
__device__ float g_wdw[256*9];
__device__ float g_pos[4][128*64];
__device__ float g_xm[2][256*1024];
__device__ float g_q[2][128*1024];
__device__ float g_k[2][128*1024];
__device__ float g_vax[2][512*1024];
__device__ float g_ax[2][512*1024];
__device__ float g_xx[2][BB*512*64];
__device__ float g_g1[(size_t)BB*256*4096];   // gate int.1, then proj results
// fp16 activation tensors
__device__ __half g_xh[(size_t)BB*256*4096];
__device__ __half g_pb[(size_t)BB*512*4096];
__device__ __half g_g2b[(size_t)BB*256*4096];

struct P32 { const float* p[32]; };

__device__ __forceinline__ float hsig(float x) {
    return fminf(fmaxf(x + 3.0f, 0.0f), 6.0f) * (1.0f / 6.0f);
}

__device__ __forceinline__ uint32_t smem_u32(const void* p) {
    uint32_t a;
    asm("{ .reg .u64 t; cvta.to.shared.u64 t, %1; cvt.u32.u64 %0, t; }" : "=r"(a) : "l"(p));
    return a;
}

__device__ __forceinline__ void mma16816(float (&d)[4], const uint32_t (&a)[4],
                                         uint32_t b0, uint32_t b1) {
    asm volatile(
        "mma.sync.aligned.m16n8k16.row.col.f32.f16.f16.f32 "
        "{%0,%1,%2,%3}, {%4,%5,%6,%7}, {%8,%9}, {%0,%1,%2,%3};"
        : "+f"(d[0]), "+f"(d[1]), "+f"(d[2]), "+f"(d[3])
        : "r"(a[0]), "r"(a[1]), "r"(a[2]), "r"(a[3]), "r"(b0), "r"(b1));
}

#define LDSM4(r, a) asm volatile( \
    "ldmatrix.sync.aligned.m8n8.x4.shared.b16 {%0,%1,%2,%3}, [%4];" \
    : "=r"((r)[0]),"=r"((r)[1]),"=r"((r)[2]),"=r"((r)[3]) : "r"(a))
#define LDSM4T(r, a) asm volatile( \
    "ldmatrix.sync.aligned.m8n8.x4.trans.shared.b16 {%0,%1,%2,%3}, [%4];" \
    : "=r"((r)[0]),"=r"((r)[1]),"=r"((r)[2]),"=r"((r)[3]) : "r"(a))
#define CP16(d, s) asm volatile( \
    "cp.async.cg.shared.global [%0], [%1], 16;" :: "r"(d), "l"(s))
#define CP_COMMIT() asm volatile("cp.async.commit_group;")
#define CP_WAIT(n)  asm volatile("cp.async.wait_group %0;" :: "n"(n))

__device__ __forceinline__ uint32_t hpack(float a, float b) {
    __half2 t = __floats2half2_rn(a, b);
    return *reinterpret_cast<uint32_t*>(&t);
}

// ---------------- prep ----------------
__global__ void prep_kernel(P32 ps) {
    int i = blockIdx.x * 256 + threadIdx.x;
    if (i < 196608) {                       // Wqkv fp32
        int r = i >> 8, k = i & 255;
        float v;
        if (r < 128)      v = ps.p[2][r]     * ps.p[1][r*256+k];
        else if (r < 256) v = ps.p[5][r-128] * ps.p[4][(r-128)*256+k];
        else              v = ps.p[8][r-256] * ps.p[7][(r-256)*256+k];
        g_Wqkv[i] = v; return;
    }
    i -= 196608;
    if (i < 196608) {                       // Wvg1 fp16
        int r = i >> 8, k = i & 255;
        float v = (r < 512) ? ps.p[8][r] * ps.p[7][r*256+k]
                            : ps.p[24][r-512] * ps.p[23][(r-512)*256+k];
        g_Wvg1_h[i] = __float2half_rn(v);
        return;
    }
    i -= 196608;
    if (i < 262144) { int r = i >> 9; g_Wxx[0][i] = ps.p[15][r] * ps.p[14][i]; return; }
    i -= 262144;
    if (i < 262144) { int r = i >> 9; g_Wxx[1][i] = ps.p[18][r] * ps.p[17][i]; return; }
    i -= 262144;
    if (i < 196608) {                       // Wfin fp16
        int r = i / 768, c = i % 768;
        float v = (c < 512) ? ps.p[21][r] * ps.p[20][r*512+c]
                            : ps.p[30][r] * ps.p[29][r*256+(c-512)];
        g_Wfin_h[i] = __float2half_rn(v);
        return;
    }
    i -= 196608;
    if (i < 2304) { g_wdw[i] = ps.p[27][i/9] * ps.p[26][i]; return; }
    i -= 2304;
    if (i < 32768) {
        int t = i >> 13, rest = i & 8191;
        int c = rest >> 6, n = rest & 63;
        float coord = 0.25f * (float)n - 0.375f;
        coord = fminf(fmaxf(coord, 0.0f), 15.0f);
        int lo = (int)floorf(coord);
        int hi = min(lo + 1, 15);
        float tf = coord - (float)lo;
        const float* src = ps.p[10 + t];
        g_pos[t][c*64 + n] = src[c*16+lo] * (1.0f - tf) + src[c*16+hi] * tf;
    }
}

// ---------------- reduce + x fp16 ----------------
__global__ void reduce_kernel(const float* __restrict__ x) {
    int bc = blockIdx.x;
    int b = bc >> 8, c = bc & 255;
    __shared__ float sm[64 * 65];
    int t = threadIdx.x;
    const float* xp = x + (size_t)bc * 4096;
    for (int i = t; i < 4096; i += 256)
        sm[(i >> 6) * 65 + (i & 63)] = xp[i];
    __syncthreads();
    if (t < 64) {
        float s = 0.f;
        #pragma unroll
        for (int w = 0; w < 64; w++) s += sm[t*65 + w];
        g_xm[0][c*1024 + b*64 + t] = s * (1.0f/64.0f);
    } else if (t < 128) {
        int w = t - 64;
        float s = 0.f;
        #pragma unroll
        for (int h = 0; h < 64; h++) s += sm[h*65 + w];
        g_xm[1][c*1024 + b*64 + w] = s * (1.0f/64.0f);
    }
    for (int i = t; i < 4096; i += 256)
        g_xh[(size_t)bc * 4096 + i] = __float2half_rn(sm[(i >> 6) * 65 + (i & 63)]);
}

// ---------------- axial attention ----------------
__global__ void attn_kernel() {
    int bid = blockIdx.x;
    int br = bid >> 7, b = (bid >> 3) & 15, h = bid & 7;
    __shared__ float qs[16][64], ks[16][64], vs[64][64], ps[64][65];
    int t = threadIdx.x;
    #pragma unroll
    for (int kd = 0; kd < 16; kd++) {
        qs[kd][t] = g_q[br][(h*16+kd)*1024 + b*64 + t];
        ks[kd][t] = g_k[br][(h*16+kd)*1024 + b*64 + t];
    }
    for (int d = 0; d < 64; d++)
        vs[d][t] = g_vax[br][(h*64+d)*1024 + b*64 + t];
    __syncthreads();
    float qreg[16];
    #pragma unroll
    for (int kd = 0; kd < 16; kd++) qreg[kd] = qs[kd][t];
    float mx = -1e30f;
    for (int m = 0; m < 64; m++) {
        float s = 0.f;
        #pragma unroll
        for (int kd = 0; kd < 16; kd++) s = fmaf(qreg[kd], ks[kd][m], s);
        s *= 0.25f;
        ps[t][m] = s;
        mx = fmaxf(mx, s);
    }
    float sum = 0.f;
    for (int m = 0; m < 64; m++) {
        float e = __expf(ps[t][m] - mx);
        ps[t][m] = e;
        sum += e;
    }
    float inv = 1.0f / sum;
    for (int d = 0; d < 64; d++) {
        float o = 0.f;
        for (int m = 0; m < 64; m++) o = fmaf(ps[t][m], vs[d][m], o);
        g_ax[br][(h*64+d)*1024 + b*64 + t] = o * inv;
    }
}

// ---------------- depthwise -> g2 fp16 ----------------
__global__ void dw_kernel(const float* __restrict__ b_dw) {
    int bc = blockIdx.x;
    int c = bc & 255;
    __shared__ float sm[64][65];
    const float* gp = &g_g1[(size_t)bc * 4096];
    int t = threadIdx.x;
    for (int i = t; i < 4096; i += 256) sm[i >> 6][i & 63] = gp[i];
    __syncthreads();
    float w9[9];
    #pragma unroll
    for (int j = 0; j < 9; j++) w9[j] = g_wdw[c*9 + j];
    float bias = b_dw[c];
    for (int i = t; i < 4096; i += 256) {
        int h = i >> 6, w = i & 63;
        float s = 0.f;
        #pragma unroll
        for (int di = 0; di < 3; di++) {
            int hh = h + di - 1;
            if ((unsigned)hh >= 64u) continue;
            #pragma unroll
            for (int dj = 0; dj < 3; dj++) {
                int ww = w + dj - 1;
                if ((unsigned)ww >= 64u) continue;
                s = fmaf(sm[hh][ww], w9[di*3 + dj], s);
            }
        }
        g_g2b[(size_t)bc * 4096 + i] = __float2half_rn(fmaxf(s + bias, 0.0f));
    }
}

// ---------------- small SIMT GEMM (modes 0 & 2) ----------------
#define BM 128
#define BN 64
#define BK 16

__device__ __forceinline__ void rank1(float (&A)[8][4], float4 a0, float4 a1, float4 b) {
    float ar[8] = {a0.x, a0.y, a0.z, a0.w, a1.x, a1.y, a1.z, a1.w};
    #pragma unroll
    for (int r = 0; r < 8; r++) {
        A[r][0] = fmaf(ar[r], b.x, A[r][0]);
        A[r][1] = fmaf(ar[r], b.y, A[r][1]);
        A[r][2] = fmaf(ar[r], b.z, A[r][2]);
        A[r][3] = fmaf(ar[r], b.w, A[r][3]);
    }
}

template <int MODE>
__global__ void __launch_bounds__(256, 2) gemm_k(
        const float* __restrict__ b0, const float* __restrict__ b1,
        const float* __restrict__ b2) {
    constexpr int K = (MODE == 0) ? 256 : 512;
    __shared__ float As[BK][BM + 4];
    __shared__ float Bs[BK][BN + 4];
    const int tid = threadIdx.x;
    const int bx = blockIdx.x, by = blockIdx.y, bz = blockIdx.z;
    const int ty8 = (tid >> 4) << 3;
    const int tx4 = (tid & 15) << 2;
    const int m0 = by * BM;
    const int pt = bx * BN;
    const float* Wm = (MODE == 0) ? g_Wqkv : g_Wxx[bz];
    const int wml = tid >> 1;
    const int wkg = (tid & 1) * 8;
    const int xkk = tid >> 4;
    const int xpl = (tid & 15) << 2;

    float acc[8][4];
    #pragma unroll
    for (int r = 0; r < 8; r++)
        #pragma unroll
        for (int j = 0; j < 4; j++) acc[r][j] = 0.f;

    for (int kt = 0; kt < K; kt += BK) {
        const float* wp = &Wm[(m0 + wml) * K + kt + wkg];
        float4 w0 = *(const float4*)wp;
        float4 w1 = *(const float4*)(wp + 4);
        int k = kt + xkk;
        float4 xv;
        if (MODE == 0) {
            xv = *(const float4*)&g_xm[bz][k*1024 + pt + xpl];
        } else {
            float4 t4 = *(const float4*)&g_ax[bz][k*1024 + pt + xpl];
            xv.x = fmaxf(t4.x, 0.f); xv.y = fmaxf(t4.y, 0.f);
            xv.z = fmaxf(t4.z, 0.f); xv.w = fmaxf(t4.w, 0.f);
        }
        __syncthreads();
        As[wkg+0][wml] = w0.x; As[wkg+1][wml] = w0.y;
        As[wkg+2][wml] = w0.z; As[wkg+3][wml] = w0.w;
        As[wkg+4][wml] = w1.x; As[wkg+5][wml] = w1.y;
        As[wkg+6][wml] = w1.z; As[wkg+7][wml] = w1.w;
        *(float4*)&Bs[xkk][xpl] = xv;
        __syncthreads();
        #pragma unroll
        for (int u = 0; u < BK; u++) {
            float4 a0 = *(const float4*)&As[u][ty8];
            float4 a1 = *(const float4*)&As[u][ty8 + 4];
            float4 bv = *(const float4*)&Bs[u][tx4];
            rank1(acc, a0, a1, bv);
        }
    }

    #pragma unroll
    for (int r = 0; r < 8; r++) {
        int m = m0 + ty8 + r;
        if (MODE == 0) {
            float4 o;
            if (m < 128) {
                float4 pv = *(const float4*)&g_pos[bz ? 2 : 0][m*64 + tx4];
                float bb = b0[m];
                o.x = acc[r][0] + bb + pv.x; o.y = acc[r][1] + bb + pv.y;
                o.z = acc[r][2] + bb + pv.z; o.w = acc[r][3] + bb + pv.w;
                *(float4*)&g_q[bz][m*1024 + pt + tx4] = o;
            } else if (m < 256) {
                int mm = m - 128;
                float4 pv = *(const float4*)&g_pos[bz ? 3 : 1][mm*64 + tx4];
                float bb = b1[mm];
                o.x = acc[r][0] + bb + pv.x; o.y = acc[r][1] + bb + pv.y;
                o.z = acc[r][2] + bb + pv.z; o.w = acc[r][3] + bb + pv.w;
                *(float4*)&g_k[bz][mm*1024 + pt + tx4] = o;
            } else {
                int mm = m - 256;
                float bb = b2[mm];
                o.x = acc[r][0] + bb; o.y = acc[r][1] + bb;
                o.z = acc[r][2] + bb; o.w = acc[r][3] + bb;
                *(float4*)&g_vax[bz][mm*1024 + pt + tx4] = o;
            }
        } else {
            float bb = (bz ? b2 : b1)[m];
            float4 o;
            o.x = acc[r][0] + bb; o.y = acc[r][1] + bb;
            o.z = acc[r][2] + bb; o.w = acc[r][3] + bb;
            int bidx = pt >> 6;
            *(float4*)&g_xx[bz][(bidx*512 + m)*64 + tx4] = o;
        }
    }
}

// ---------------- HMMA GEMM (modes 1, 3, 4) ----------------
// CTA 256 thr, tile 128(ch) x 128(px); warps 4x2, warp tile 32x64.
// Pure fp16 x fp16, fp32 acc (1 term).
// Stage layout: A 0 (128x72 halves, 144B stride) | B 18432 (64x136, 272B)
// Stage stride 35840 B; 2 stages.
#define MM_SMEM (2 * 35840)

template <int MODE>
__global__ void __launch_bounds__(256) mm_gemm(
        const float* __restrict__ bias0,
        const float* __restrict__ bias1,
        float* __restrict__ outp) {
    extern __shared__ char smem[];
    constexpr int K       = (MODE == 3) ? 512 : 256;
    constexpr int NC      = K / 64;
    constexpr int KSTRIDE = (MODE == 1) ? 256 : 768;
    constexpr int KOFF    = (MODE == 4) ? 512 : 0;
    constexpr int CH      = (MODE == 3) ? 512 : 256;
    const int tid = threadIdx.x, lane = tid & 31, wid = tid >> 5;
    const int wm = wid & 3, wn = wid >> 2;
    const int m0 = blockIdx.x * 128;
    const int pt = blockIdx.y;
    const int b_ = pt >> 5;
    const int hw0 = (pt & 31) << 7;

    const uint32_t sb = smem_u32(smem);
    const __half* Wh = (MODE == 1) ? g_Wvg1_h : g_Wfin_h;
    const __half* Bg = (MODE == 1) ? g_xh : (MODE == 3) ? g_pb : g_g2b;

    float acc[2][8][4];
    #pragma unroll
    for (int mf = 0; mf < 2; mf++)
        #pragma unroll
        for (int nf = 0; nf < 8; nf++)
            #pragma unroll
            for (int j = 0; j < 4; j++) acc[mf][nf][j] = 0.f;

    auto FILL = [&](int c) {
        const uint32_t st = sb + (uint32_t)(c & 1) * 35840u;
        const int kc = c * 64;
        #pragma unroll
        for (int i = 0; i < 4; i++) {          // A: 128x64 fp16
            int idx = tid + i * 256;
            int m = idx >> 3, k8 = (idx & 7) << 3;
            size_t g = (size_t)(m0 + m) * KSTRIDE + KOFF + kc + k8;
            uint32_t d = st + (uint32_t)(m * 144 + k8 * 2);
            CP16(d, Wh + g);
        }
        #pragma unroll
        for (int i = 0; i < 4; i++) {          // B: 64k x 128px fp16
            int idx = tid + i * 256;
            int k = idx >> 4, px8 = (idx & 15) << 3;
            size_t g = (((size_t)(b_ * CH + kc + k)) << 12) + hw0 + px8;
            uint32_t d = st + 18432u + (uint32_t)(k * 272 + px8 * 2);
            CP16(d, Bg + g);
        }
    };

    FILL(0); CP_COMMIT();
    for (int c = 0; c < NC; c++) {
        if (c + 1 < NC) { FILL(c + 1); CP_COMMIT(); CP_WAIT(1); }
        else            { CP_WAIT(0); }
        __syncthreads();
        const uint32_t st = sb + (uint32_t)(c & 1) * 35840u;
        #pragma unroll
        for (int kk = 0; kk < 64; kk += 16) {
            uint32_t ah[2][4];
            uint32_t aoff = st + (uint32_t)(((wm * 32 + (lane & 15)) * 72
                              + kk + ((lane >> 4) << 3)) * 2);
            LDSM4(ah[0], aoff);
            LDSM4(ah[1], aoff + 16u * 144u);
            #pragma unroll
            for (int np = 0; np < 4; np++) {
                uint32_t bh[4];
                uint32_t boff = st + 18432u + (uint32_t)(
                    ((kk + (lane & 7) + (((lane >> 3) & 1) << 3)) * 136
                     + wn * 64 + np * 16 + ((lane >> 4) << 3)) * 2);
                LDSM4T(bh, boff);
                #pragma unroll
                for (int mf = 0; mf < 2; mf++) {
                    mma16816(acc[mf][2*np],   ah[mf], bh[0], bh[1]);
                    mma16816(acc[mf][2*np+1], ah[mf], bh[2], bh[3]);
                }
            }
        }
        __syncthreads();
    }

    // ---- epilogue ----
    #pragma unroll
    for (int mf = 0; mf < 2; mf++) {
        int r0 = m0 + wm * 32 + mf * 16 + (lane >> 2);
        #pragma unroll
        for (int nf = 0; nf < 8; nf++) {
            int pxg = hw0 + wn * 64 + nf * 8 + ((lane & 3) << 1);
            #pragma unroll
            for (int half = 0; half < 2; half++) {
                int m = r0 + half * 8;
                float v0 = acc[mf][nf][half * 2 + 0];
                float v1 = acc[mf][nf][half * 2 + 1];
                if (MODE == 1) {
                    if (m < 512) {
                        float bb = bias0[m];
                        int hh = pxg >> 6, ww = pxg & 63;
                        float xr = g_xx[0][(b_*512 + m)*64 + hh];
                        float2 xc = *(const float2*)&g_xx[1][(b_*512 + m)*64 + ww];
                        float p0 = fmaxf(v0 + bb + xr + xc.x, 0.f);
                        float p1 = fmaxf(v1 + bb + xr + xc.y, 0.f);
                        size_t o = (((size_t)(b_*512 + m)) << 12) + pxg;
                        *(uint32_t*)&g_pb[o] = hpack(p0, p1);
                    } else {
                        float bb = bias1[m - 512];
                        float2 o2 = {v0 + bb, v1 + bb};
                        *(float2*)&g_g1[(((size_t)((b_ << 8) + m - 512)) << 12) + pxg] = o2;
                    }
                } else if (MODE == 3) {
                    float bb = bias0[m];
                    float2 o2 = {v0 + bb, v1 + bb};
                    *(float2*)&g_g1[(((size_t)((b_ << 8) + m)) << 12) + pxg] = o2;
                } else {
                    float bb = bias1[m];
                    float2 pr = *(const float2*)&g_g1[(((size_t)((b_ << 8) + m)) << 12) + pxg];
                    float2 o2 = {pr.x * hsig(v0 + bb), pr.y * hsig(v1 + bb)};
                    *(float2*)&outp[(((size_t)((b_ << 8) + m)) << 12) + pxg] = o2;
                }
            }
        }
    }
}

// ---------------------------------------------------------------------------
extern "C" void kernel_launch(void* const* d_in, const int* in_sizes, int n_in,
                              void* d_out, int out_size) {
    (void)in_sizes; (void)n_in; (void)out_size;
    P32 ps;
    for (int i = 0; i < 32; i++) ps.p[i] = (const float*)d_in[i];
    const float* x      = ps.p[0];
    const float* bq     = ps.p[3];
    const float* bk     = ps.p[6];
    const float* bv     = ps.p[9];
    const float* b_row  = ps.p[16];
    const float* b_col  = ps.p[19];
    const float* b_proj = ps.p[22];
    const float* b_sc   = ps.p[25];
    const float* b_dw   = ps.p[28];
    const float* b_pw   = ps.p[31];
    float* out = (float*)d_out;

    cudaFuncSetAttribute(mm_gemm<1>, cudaFuncAttributeMaxDynamicSharedMemorySize, MM_SMEM);
    cudaFuncSetAttribute(mm_gemm<3>, cudaFuncAttributeMaxDynamicSharedMemorySize, MM_SMEM);
    cudaFuncSetAttribute(mm_gemm<4>, cudaFuncAttributeMaxDynamicSharedMemorySize, MM_SMEM);

    prep_kernel<<<4489, 256>>>(ps);
    reduce_kernel<<<4096, 256>>>(x);
    gemm_k<0><<<dim3(16, 6, 2), 256>>>(bq, bk, bv);
    attn_kernel<<<256, 64>>>();
    gemm_k<2><<<dim3(16, 4, 2), 256>>>(nullptr, b_row, b_col);
    mm_gemm<1><<<dim3(6, 512), 256, MM_SMEM>>>(bv, b_sc, nullptr);
    dw_kernel<<<4096, 256>>>(b_dw);
    mm_gemm<3><<<dim3(2, 512), 256, MM_SMEM>>>(b_proj, nullptr, nullptr);
    mm_gemm<4><<<dim3(2, 512), 256, MM_SMEM>>>(nullptr, b_pw, out);
}